// round 6
// baseline (speedup 1.0000x reference)
#include <cuda_runtime.h>
#include <cstdint>

#define BB 4
#define TT 2048
#define DD 1024
#define HH 16
#define DKK 64
#define SCALE_ 0.125f
#define EPS_LN_ 1e-5f
#define EPS_NORM_ 1e-8f

// within-8 column permutation: natural col c -> stored position perm8(c)
// order [0,4,1,5,2,6,3,7]; perm8(t)=2t, perm8(t+4)=2t+1 for t<4
__host__ __device__ __forceinline__ constexpr int perm8(int c) {
    return ((c & 3) << 1) | ((c >> 2) & 1);
}

// ---------------- scratch ----------------
__device__ float g_xn[BB * TT * DD];           // LN output, D-permuted
__device__ float g_q[BB * HH * TT * DKK];      // DK-permuted
__device__ float g_k[BB * HH * TT * DKK];      // DK-permuted
__device__ float g_v[BB * HH * TT * DKK];      // natural [B,H,T,DK]
__device__ float g_ao[BB * TT * DD];           // attention out, D-permuted
__device__ float g_wc[4 * DD * DD];            // tf32 weights, k-dim permuted
__device__ unsigned char g_cmask[BB * TT];
__device__ int g_flags[3];

// ---------------- helpers ----------------
__device__ __forceinline__ unsigned f2tf(float x) {
    unsigned r;
    asm("cvt.rna.tf32.f32 %0, %1;" : "=r"(r) : "f"(x));
    return r;
}
__device__ __forceinline__ float f2tff(float x) { return __uint_as_float(f2tf(x)); }

__device__ __forceinline__ void mma_tf32(float* d, const unsigned* a,
                                         const unsigned* b, const float* c) {
    asm volatile(
        "mma.sync.aligned.m16n8k8.row.col.f32.tf32.tf32.f32 "
        "{%0,%1,%2,%3}, {%4,%5,%6,%7}, {%8,%9}, {%10,%11,%12,%13};"
        : "=f"(d[0]), "=f"(d[1]), "=f"(d[2]), "=f"(d[3])
        : "r"(a[0]), "r"(a[1]), "r"(a[2]), "r"(a[3]),
          "r"(b[0]), "r"(b[1]),
          "f"(c[0]), "f"(c[1]), "f"(c[2]), "f"(c[3]));
}
__device__ __forceinline__ void cp_async16(uint32_t saddr, const void* gptr) {
    asm volatile("cp.async.cg.shared.global [%0], [%1], 16;\n" :: "r"(saddr), "l"(gptr));
}
__device__ __forceinline__ void cp_commit() { asm volatile("cp.async.commit_group;\n" ::); }
__device__ __forceinline__ void cp_wait0()  { asm volatile("cp.async.wait_group 0;\n" ::); }
__device__ __forceinline__ uint32_t smem_u32(const void* p) {
    return (uint32_t)__cvta_generic_to_shared(p);
}

// ---------------- mask detection / canonicalization ----------------
__global__ void detect_mask_kernel(const unsigned char* __restrict__ m) {
    if (threadIdx.x == 0) { g_flags[0] = 0; g_flags[1] = 0; g_flags[2] = 0; }
    __syncthreads();
    int a = 0, bhi = 0, c = 0;
    for (int i = threadIdx.x; i < BB * TT; i += blockDim.x) {
        unsigned char v = m[i];
        if (v) {
            int r = i & 3;
            if (r == 0) a = 1;
            else if (r == 1) c = 1;
            else bhi = 1;
        }
    }
    if (a)   atomicOr(&g_flags[0], 1);
    if (bhi) atomicOr(&g_flags[1], 1);
    if (c)   atomicOr(&g_flags[2], 1);
}
__global__ void convert_mask_kernel(const void* __restrict__ m) {
    int i = blockIdx.x * blockDim.x + threadIdx.x;
    if (i >= BB * TT) return;
    int A = g_flags[0], Bf = g_flags[1], C = g_flags[2];
    unsigned char out;
    if (A && !Bf && !C)      out = (((const int*)m)[i] != 0);
    else if (!A && Bf)       out = (((const float*)m)[i] != 0.0f);
    else                     out = (((const unsigned char*)m)[i] != 0);
    g_cmask[i] = out;
}

// ---------------- weight conversion: tf32 round + k-dim perm ----------------
__global__ __launch_bounds__(256) void wconv_kernel(
    const float* __restrict__ w0, const float* __restrict__ w1,
    const float* __restrict__ w2, const float* __restrict__ w3) {
    const float* src = (blockIdx.y == 0) ? w0 : (blockIdx.y == 1) ? w1
                     : (blockIdx.y == 2) ? w2 : w3;
    float* dst = g_wc + (size_t)blockIdx.y * DD * DD;
    size_t i = ((size_t)blockIdx.x * 256 + threadIdx.x) * 4;
    float4 v = *(const float4*)&src[i];
    size_t base = (i & ~(size_t)7) + ((i & 4) >> 2);
    dst[base + 0] = f2tff(v.x);
    dst[base + 2] = f2tff(v.y);
    dst[base + 4] = f2tff(v.z);
    dst[base + 6] = f2tff(v.w);
}

// ---------------- LayerNorm: tf32 round + D-perm ----------------
__global__ __launch_bounds__(256) void ln_kernel(
    const float* __restrict__ x, const float* __restrict__ g,
    const float* __restrict__ b) {
    __shared__ float red_s[8], red_ss[8];
    int row = blockIdx.x;
    int tid = threadIdx.x;
    const float* xr = x + (size_t)row * DD;
    float4 xv = *(const float4*)&xr[tid * 4];
    float s  = xv.x + xv.y + xv.z + xv.w;
    float ss = xv.x*xv.x + xv.y*xv.y + xv.z*xv.z + xv.w*xv.w;
    #pragma unroll
    for (int o = 16; o > 0; o >>= 1) {
        s  += __shfl_xor_sync(~0u, s, o);
        ss += __shfl_xor_sync(~0u, ss, o);
    }
    int warp = tid >> 5, lane = tid & 31;
    if (lane == 0) { red_s[warp] = s; red_ss[warp] = ss; }
    __syncthreads();
    if (warp == 0) {
        s  = (lane < 8) ? red_s[lane]  : 0.f;
        ss = (lane < 8) ? red_ss[lane] : 0.f;
        #pragma unroll
        for (int o = 4; o > 0; o >>= 1) {
            s  += __shfl_xor_sync(~0u, s, o);
            ss += __shfl_xor_sync(~0u, ss, o);
        }
        if (lane == 0) { red_s[0] = s; red_ss[0] = ss; }
    }
    __syncthreads();
    float mu  = red_s[0] * (1.0f / DD);
    float var = red_ss[0] * (1.0f / DD) - mu * mu;
    float inv = rsqrtf(var + EPS_LN_);
    float4 gv = *(const float4*)&g[tid * 4];
    float4 bv = *(const float4*)&b[tid * 4];
    float* dst = &g_xn[(size_t)row * DD + (tid & ~1) * 4 + (tid & 1)];
    dst[0] = f2tff((xv.x - mu) * inv * gv.x + bv.x);
    dst[2] = f2tff((xv.y - mu) * inv * gv.y + bv.y);
    dst[4] = f2tff((xv.z - mu) * inv * gv.z + bv.z);
    dst[6] = f2tff((xv.w - mu) * inv * gv.w + bv.w);
}

// ---------------- tf32 GEMM, cp.async double-buffered, float2 frags --------
#define GSTR 40
#define GTILE (128 * GSTR)
__global__ __launch_bounds__(256) void gemm_tc_kernel(
    const float* __restrict__ b0, const float* __restrict__ b1,
    const float* __restrict__ b2, int mode_base, float* __restrict__ dout) {
    extern __shared__ float gsm[];
    int mode = (mode_base == 3) ? 3 : (int)blockIdx.z;
    const float* W = g_wc + (size_t)mode * DD * DD;
    const float* bias = (mode == 1) ? b1 : (mode == 2) ? b2 : b0;
    const float* Aptr = (mode < 3) ? g_xn : g_ao;

    int tid  = threadIdx.x;
    int wid  = tid >> 5;
    int lane = tid & 31;
    int g = lane >> 2, t = lane & 3;
    int wm = (wid >> 2) * 64;
    int wn = (wid & 3) * 32;
    int m0 = blockIdx.y * 128;
    int n0 = blockIdx.x * 128;
    uint32_t sbase = smem_u32(gsm);

    float acc[4][4][4];
    #pragma unroll
    for (int i = 0; i < 4; i++)
        #pragma unroll
        for (int j = 0; j < 4; j++)
            #pragma unroll
            for (int e = 0; e < 4; e++) acc[i][j][e] = 0.f;

    auto load_stage = [&](int k0, int st) {
        #pragma unroll
        for (int p = 0; p < 4; p++) {
            int slot = tid + p * 256;
            int row  = slot >> 3;
            int col4 = (slot & 7) * 4;
            cp_async16(sbase + (uint32_t)((st * GTILE + row * GSTR + col4) * 4),
                       &Aptr[(size_t)(m0 + row) * DD + k0 + col4]);
            cp_async16(sbase + (uint32_t)(((2 + st) * GTILE + row * GSTR + col4) * 4),
                       &W[(size_t)(n0 + row) * DD + k0 + col4]);
        }
        cp_commit();
    };

    load_stage(0, 0);
    for (int it = 0; it < DD / 32; it++) {
        int cur = it & 1;
        cp_wait0();
        __syncthreads();
        if (it < DD / 32 - 1) load_stage((it + 1) * 32, cur ^ 1);
        const float* As = gsm + cur * GTILE;
        const float* Bs = gsm + (2 + cur) * GTILE;
        #pragma unroll
        for (int ks = 0; ks < 4; ks++) {
            int kc = ks * 8 + 2 * t;               // permuted {t, t+4} adjacent
            unsigned bf[4][2];
            #pragma unroll
            for (int n = 0; n < 4; n++) {
                float2 bb = *(const float2*)&Bs[(wn + n * 8 + g) * GSTR + kc];
                bf[n][0] = __float_as_uint(bb.x);
                bf[n][1] = __float_as_uint(bb.y);
            }
            #pragma unroll
            for (int mI = 0; mI < 4; mI++) {
                int rb = wm + mI * 16;
                float2 aA = *(const float2*)&As[(rb + g) * GSTR + kc];
                float2 aB = *(const float2*)&As[(rb + g + 8) * GSTR + kc];
                unsigned af[4] = {__float_as_uint(aA.x), __float_as_uint(aB.x),
                                  __float_as_uint(aA.y), __float_as_uint(aB.y)};
                #pragma unroll
                for (int n = 0; n < 4; n++)
                    mma_tf32(acc[mI][n], af, bf[n], acc[mI][n]);
            }
        }
    }

    #pragma unroll
    for (int mI = 0; mI < 4; mI++) {
        int r0 = m0 + wm + mI * 16 + g;
        int bi0 = r0 >> 11, t0 = r0 & (TT - 1);
        #pragma unroll
        for (int n = 0; n < 4; n++) {
            int e = n0 + wn + n * 8 + 2 * t;       // natural pair (e, e+1)
            float bb0 = bias[e], bb1 = bias[e + 1];
            float v00 = acc[mI][n][0] + bb0, v01 = acc[mI][n][1] + bb1;
            float v10 = acc[mI][n][2] + bb0, v11 = acc[mI][n][3] + bb1;
            if (mode == 3) {
                *(float2*)&dout[(size_t)r0 * DD + e] =
                    make_float2(v00 * 0.5f, v01 * 0.5f);
                *(float2*)&dout[(size_t)(r0 + 8) * DD + e] =
                    make_float2(v10 * 0.5f, v11 * 0.5f);
            } else {
                int h = e >> 6, dk = e & 63;
                size_t base0 = (((size_t)(bi0 * HH + h) * TT + t0) << 6);
                size_t base1 = base0 + (8 << 6);
                if (mode == 2) {                   // V natural, tf32-rounded
                    *(float2*)&g_v[base0 + dk] = make_float2(f2tff(v00), f2tff(v01));
                    *(float2*)&g_v[base1 + dk] = make_float2(f2tff(v10), f2tff(v11));
                } else {                           // Q,K DK-permuted scatter
                    float* C = (mode == 0) ? g_q : g_k;
                    int dkp = (dk & ~7) | perm8(dk & 7);   // pair -> dkp, dkp+2
                    C[base0 + dkp]     = v00;
                    C[base0 + dkp + 2] = v01;
                    C[base1 + dkp]     = v10;
                    C[base1 + dkp + 2] = v11;
                }
            }
        }
    }
}

// ---------------- L2 normalize (order-invariant over permuted rows) -------
__global__ __launch_bounds__(256) void l2norm_kernel() {
    int warp = (blockIdx.x * blockDim.x + threadIdx.x) >> 5;
    int lane = threadIdx.x & 31;
    float* base = (blockIdx.y == 0) ? g_q : g_k;
    float* p = base + (size_t)warp * DKK + lane * 2;
    float2 v = *(float2*)p;
    float ss = v.x * v.x + v.y * v.y;
    #pragma unroll
    for (int o = 16; o > 0; o >>= 1) ss += __shfl_xor_sync(~0u, ss, o);
    float n = sqrtf(ss);
    float inv = 1.0f / fmaxf(n, EPS_NORM_);
    v.x = f2tff(v.x * inv); v.y = f2tff(v.y * inv);
    *(float2*)p = v;
}

// ---------------- Flash attention: 128 queries/block, 2 sequential halves --
// Each block processes two 64-query halves against every loaded K/V tile,
// halving total K/V shared/L2 traffic. P goes in a dedicated warp-private
// buffer so K stays live across both halves (no extra block barriers).
#define ASTR 72
#define ATILE (64 * ASTR)
#define P_OFF (4 * ATILE)
#define MSK_OFF (P_OFF + 64 * ASTR)
#define ASMEM (MSK_OFF * 4 + TT)     // bytes: K0 K1 V0 V1 + P + mask
__global__ __launch_bounds__(128) void attn_tc_kernel() {
    extern __shared__ float asm_[];
    float* Ps = asm_ + P_OFF;
    unsigned char* Msk = (unsigned char*)(asm_ + MSK_OFF);

    int bh = blockIdx.y;
    int bi = bh >> 4;
    int h  = bh & 15;
    int qt = blockIdx.x;               // 128-query tile
    int tid = threadIdx.x;
    int wid = tid >> 5;
    int lane = tid & 31;
    int g = lane >> 2, t = lane & 3;
    int wg = wid * 16;
    uint32_t sbase = smem_u32(asm_);

    ((uint4*)Msk)[tid] = ((const uint4*)(g_cmask + bi * TT))[tid];

    // resident Q fragments for both halves (DK-permuted -> float2 loads)
    unsigned qa[2][8][4];
    #pragma unroll
    for (int hq = 0; hq < 2; hq++) {
        const float* qp0 =
            g_q + (((size_t)(bh * TT + qt * 128 + hq * 64 + wg + g)) << 6);
        const float* qp1 = qp0 + (8 << 6);
        #pragma unroll
        for (int ks = 0; ks < 8; ks++) {
            float2 qA = *(const float2*)&qp0[ks * 8 + 2 * t];
            float2 qB = *(const float2*)&qp1[ks * 8 + 2 * t];
            qa[hq][ks][0] = __float_as_uint(qA.x);
            qa[hq][ks][1] = __float_as_uint(qB.x);
            qa[hq][ks][2] = __float_as_uint(qA.y);
            qa[hq][ks][3] = __float_as_uint(qB.y);
        }
    }

    float o_acc[2][8][4];
    #pragma unroll
    for (int hq = 0; hq < 2; hq++)
        #pragma unroll
        for (int n = 0; n < 8; n++)
            #pragma unroll
            for (int e = 0; e < 4; e++) o_acc[hq][n][e] = 0.f;
    float psum[2][2] = {{0.f, 0.f}, {0.f, 0.f}};

    const float* kbase = g_k + (((size_t)bh * TT) << 6);
    const float* vbase = g_v + (((size_t)bh * TT) << 6);

    auto load_kv = [&](int kt, int st) {
        const float* kb = kbase + ((size_t)(kt * 64) << 6);
        const float* vb = vbase + ((size_t)(kt * 64) << 6);
        #pragma unroll
        for (int p = 0; p < 8; p++) {
            int slot = tid + p * 128;
            int row  = slot >> 4;
            int col4 = (slot & 15) * 4;
            cp_async16(sbase + (uint32_t)((st * ATILE + row * ASTR + col4) * 4),
                       &kb[(row << 6) + col4]);
            cp_async16(sbase + (uint32_t)(((2 + st) * ATILE + row * ASTR + col4) * 4),
                       &vb[(row << 6) + col4]);
        }
        cp_commit();
    };

    load_kv(0, 0);
    for (int kt = 0; kt < TT / 64; kt++) {
        int cur = kt & 1;
        cp_wait0();
        __syncthreads();
        if (kt < TT / 64 - 1) load_kv(kt + 1, cur ^ 1);

        const float* Ks = asm_ + cur * ATILE;
        const float* Vs = asm_ + (2 + cur) * ATILE;
        const unsigned char* mrow = Msk + kt * 64;

        #pragma unroll
        for (int hq = 0; hq < 2; hq++) {
            // S = Q.K^T (float2 b-frags from DK-permuted K)
            float sc[8][4];
            #pragma unroll
            for (int n = 0; n < 8; n++)
                #pragma unroll
                for (int e = 0; e < 4; e++) sc[n][e] = 0.f;
            #pragma unroll
            for (int ks = 0; ks < 8; ks++) {
                int kc = ks * 8 + 2 * t;
                #pragma unroll
                for (int n = 0; n < 8; n++) {
                    float2 kb2 = *(const float2*)&Ks[(n * 8 + g) * ASTR + kc];
                    unsigned bf[2] = {__float_as_uint(kb2.x), __float_as_uint(kb2.y)};
                    mma_tf32(sc[n], qa[hq][ks], bf, sc[n]);
                }
            }

            // static softmax weights; masked -> 0
            #pragma unroll
            for (int n = 0; n < 8; n++) {
                bool mk0 = mrow[n * 8 + 2 * t] != 0;
                bool mk1 = mrow[n * 8 + 2 * t + 1] != 0;
                sc[n][0] = mk0 ? 0.f : __expf(sc[n][0] * SCALE_);
                sc[n][1] = mk1 ? 0.f : __expf(sc[n][1] * SCALE_);
                sc[n][2] = mk0 ? 0.f : __expf(sc[n][2] * SCALE_);
                sc[n][3] = mk1 ? 0.f : __expf(sc[n][3] * SCALE_);
                psum[hq][0] += sc[n][0] + sc[n][1];
                psum[hq][1] += sc[n][2] + sc[n][3];
            }

            // P (tf32) -> dedicated warp-private rows of Ps
            #pragma unroll
            for (int n = 0; n < 8; n++) {
                int c = n * 8 + 2 * t;
                *(float2*)&Ps[(wg + g) * ASTR + c] =
                    make_float2(f2tff(sc[n][0]), f2tff(sc[n][1]));
                *(float2*)&Ps[(wg + g + 8) * ASTR + c] =
                    make_float2(f2tff(sc[n][2]), f2tff(sc[n][3]));
            }
            __syncwarp();

            // O += P.V
            #pragma unroll
            for (int ks = 0; ks < 8; ks++) {
                int kc = ks * 8;
                unsigned pa[4];
                pa[0] = __float_as_uint(Ps[(wg + g) * ASTR + kc + t]);
                pa[1] = __float_as_uint(Ps[(wg + g + 8) * ASTR + kc + t]);
                pa[2] = __float_as_uint(Ps[(wg + g) * ASTR + kc + t + 4]);
                pa[3] = __float_as_uint(Ps[(wg + g + 8) * ASTR + kc + t + 4]);
                #pragma unroll
                for (int n = 0; n < 8; n++) {
                    unsigned bf[2];
                    bf[0] = __float_as_uint(Vs[(kc + t) * ASTR + n * 8 + g]);
                    bf[1] = __float_as_uint(Vs[(kc + t + 4) * ASTR + n * 8 + g]);
                    mma_tf32(o_acc[hq][n], pa, bf, o_acc[hq][n]);
                }
            }
            __syncwarp();   // P reads done before other half / next tile writes
        }
    }

    #pragma unroll
    for (int hq = 0; hq < 2; hq++) {
        float p0 = psum[hq][0], p1 = psum[hq][1];
        p0 += __shfl_xor_sync(~0u, p0, 1);
        p0 += __shfl_xor_sync(~0u, p0, 2);
        p1 += __shfl_xor_sync(~0u, p1, 1);
        p1 += __shfl_xor_sync(~0u, p1, 2);
        float inv0 = 1.0f / p0;
        float inv1 = 1.0f / p1;
        int tq0 = qt * 128 + hq * 64 + wg + g;
        float* ob0 = g_ao + ((size_t)bi * TT + tq0) * DD + h * 64;
        float* ob1 = ob0 + 8 * DD;
        #pragma unroll
        for (int n = 0; n < 8; n++) {
            int pc = n * 8 + perm8(2 * t);        // D-perm for O-GEMM feed
            ob0[pc]     = f2tff(o_acc[hq][n][0] * inv0);
            ob0[pc + 2] = f2tff(o_acc[hq][n][1] * inv0);
            ob1[pc]     = f2tff(o_acc[hq][n][2] * inv1);
            ob1[pc + 2] = f2tff(o_acc[hq][n][3] * inv1);
        }
    }
}

// ---------------- launch ----------------
extern "C" void kernel_launch(void* const* d_in, const int* in_sizes, int n_in,
                              void* d_out, int out_size) {
    const float* x    = (const float*)d_in[0];
    const void*  mask = d_in[1];
    const float* wq = (const float*)d_in[2];
    const float* bq = (const float*)d_in[3];
    const float* wk = (const float*)d_in[4];
    const float* bk = (const float*)d_in[5];
    const float* wv = (const float*)d_in[6];
    const float* bv = (const float*)d_in[7];
    const float* wo = (const float*)d_in[8];
    const float* bo = (const float*)d_in[9];
    const float* ln_g = (const float*)d_in[10];
    const float* ln_b = (const float*)d_in[11];
    float* out = (float*)d_out;

    const int gemm_smem = 4 * GTILE * 4;          // 81920 B
    const int attn_smem = ASMEM;                  // 94208 B
    cudaFuncSetAttribute(gemm_tc_kernel,
        cudaFuncAttributeMaxDynamicSharedMemorySize, gemm_smem);
    cudaFuncSetAttribute(attn_tc_kernel,
        cudaFuncAttributeMaxDynamicSharedMemorySize, attn_smem);

    detect_mask_kernel<<<1, 256>>>((const unsigned char*)mask);
    convert_mask_kernel<<<(BB * TT + 255) / 256, 256>>>(mask);
    wconv_kernel<<<dim3(DD * DD / 1024, 4), 256>>>(wq, wk, wv, wo);
    ln_kernel<<<BB * TT, 256>>>(x, ln_g, ln_b);

    dim3 qkv_grid(DD / 128, (BB * TT) / 128, 3);
    gemm_tc_kernel<<<qkv_grid, 256, gemm_smem>>>(bq, bk, bv, 0, nullptr);

    dim3 l2grid((BB * HH * TT) / 8, 2);
    l2norm_kernel<<<l2grid, 256>>>();

    dim3 agrid(TT / 128, BB * HH);                // (16, 64)
    attn_tc_kernel<<<agrid, 128, attn_smem>>>();

    dim3 ogrid(DD / 128, (BB * TT) / 128, 1);
    gemm_tc_kernel<<<ogrid, 256, gemm_smem>>>(bo, nullptr, nullptr, 3, out);
}

// round 7
// speedup vs baseline: 1.5655x; 1.5655x over previous
#include <cuda_runtime.h>
#include <cstdint>

#define BB 4
#define TT 2048
#define DD 1024
#define HH 16
#define DKK 64
#define SCALE_ 0.125f
#define EPS_LN_ 1e-5f
#define EPS_NORM_ 1e-8f

// within-8 column permutation: natural col c -> stored position perm8(c)
// order [0,4,1,5,2,6,3,7]; perm8(t)=2t, perm8(t+4)=2t+1 for t<4
__host__ __device__ __forceinline__ constexpr int perm8(int c) {
    return ((c & 3) << 1) | ((c >> 2) & 1);
}

// ---------------- scratch ----------------
__device__ float g_xn[BB * TT * DD];           // LN output, D-permuted
__device__ float g_q[BB * HH * TT * DKK];      // DK-permuted
__device__ float g_k[BB * HH * TT * DKK];      // DK-permuted
__device__ float g_v[BB * HH * TT * DKK];      // natural [B,H,T,DK]
__device__ float g_ao[BB * TT * DD];           // attention out, D-permuted
__device__ float g_wc[4 * DD * DD];            // tf32 weights, k-dim permuted
__device__ unsigned char g_cmask[BB * TT];
__device__ int g_flags[3];

// ---------------- helpers ----------------
__device__ __forceinline__ unsigned f2tf(float x) {
    unsigned r;
    asm("cvt.rna.tf32.f32 %0, %1;" : "=r"(r) : "f"(x));
    return r;
}
__device__ __forceinline__ float f2tff(float x) { return __uint_as_float(f2tf(x)); }

__device__ __forceinline__ void mma_tf32(float* d, const unsigned* a,
                                         const unsigned* b, const float* c) {
    asm volatile(
        "mma.sync.aligned.m16n8k8.row.col.f32.tf32.tf32.f32 "
        "{%0,%1,%2,%3}, {%4,%5,%6,%7}, {%8,%9}, {%10,%11,%12,%13};"
        : "=f"(d[0]), "=f"(d[1]), "=f"(d[2]), "=f"(d[3])
        : "r"(a[0]), "r"(a[1]), "r"(a[2]), "r"(a[3]),
          "r"(b[0]), "r"(b[1]),
          "f"(c[0]), "f"(c[1]), "f"(c[2]), "f"(c[3]));
}
__device__ __forceinline__ void cp_async16(uint32_t saddr, const void* gptr) {
    asm volatile("cp.async.cg.shared.global [%0], [%1], 16;\n" :: "r"(saddr), "l"(gptr));
}
__device__ __forceinline__ void cp_commit() { asm volatile("cp.async.commit_group;\n" ::); }
__device__ __forceinline__ void cp_wait0()  { asm volatile("cp.async.wait_group 0;\n" ::); }
__device__ __forceinline__ uint32_t smem_u32(const void* p) {
    return (uint32_t)__cvta_generic_to_shared(p);
}

// ---------------- mask detection / canonicalization ----------------
__global__ void detect_mask_kernel(const unsigned char* __restrict__ m) {
    if (threadIdx.x == 0) { g_flags[0] = 0; g_flags[1] = 0; g_flags[2] = 0; }
    __syncthreads();
    int a = 0, bhi = 0, c = 0;
    for (int i = threadIdx.x; i < BB * TT; i += blockDim.x) {
        unsigned char v = m[i];
        if (v) {
            int r = i & 3;
            if (r == 0) a = 1;
            else if (r == 1) c = 1;
            else bhi = 1;
        }
    }
    if (a)   atomicOr(&g_flags[0], 1);
    if (bhi) atomicOr(&g_flags[1], 1);
    if (c)   atomicOr(&g_flags[2], 1);
}
__global__ void convert_mask_kernel(const void* __restrict__ m) {
    int i = blockIdx.x * blockDim.x + threadIdx.x;
    if (i >= BB * TT) return;
    int A = g_flags[0], Bf = g_flags[1], C = g_flags[2];
    unsigned char out;
    if (A && !Bf && !C)      out = (((const int*)m)[i] != 0);
    else if (!A && Bf)       out = (((const float*)m)[i] != 0.0f);
    else                     out = (((const unsigned char*)m)[i] != 0);
    g_cmask[i] = out;
}

// ---------------- weight conversion: tf32 round + k-dim perm ----------------
__global__ __launch_bounds__(256) void wconv_kernel(
    const float* __restrict__ w0, const float* __restrict__ w1,
    const float* __restrict__ w2, const float* __restrict__ w3) {
    const float* src = (blockIdx.y == 0) ? w0 : (blockIdx.y == 1) ? w1
                     : (blockIdx.y == 2) ? w2 : w3;
    float* dst = g_wc + (size_t)blockIdx.y * DD * DD;
    size_t i = ((size_t)blockIdx.x * 256 + threadIdx.x) * 4;
    float4 v = *(const float4*)&src[i];
    size_t base = (i & ~(size_t)7) + ((i & 4) >> 2);
    dst[base + 0] = f2tff(v.x);
    dst[base + 2] = f2tff(v.y);
    dst[base + 4] = f2tff(v.z);
    dst[base + 6] = f2tff(v.w);
}

// ---------------- LayerNorm: tf32 round + D-perm ----------------
__global__ __launch_bounds__(256) void ln_kernel(
    const float* __restrict__ x, const float* __restrict__ g,
    const float* __restrict__ b) {
    __shared__ float red_s[8], red_ss[8];
    int row = blockIdx.x;
    int tid = threadIdx.x;
    const float* xr = x + (size_t)row * DD;
    float4 xv = *(const float4*)&xr[tid * 4];
    float s  = xv.x + xv.y + xv.z + xv.w;
    float ss = xv.x*xv.x + xv.y*xv.y + xv.z*xv.z + xv.w*xv.w;
    #pragma unroll
    for (int o = 16; o > 0; o >>= 1) {
        s  += __shfl_xor_sync(~0u, s, o);
        ss += __shfl_xor_sync(~0u, ss, o);
    }
    int warp = tid >> 5, lane = tid & 31;
    if (lane == 0) { red_s[warp] = s; red_ss[warp] = ss; }
    __syncthreads();
    if (warp == 0) {
        s  = (lane < 8) ? red_s[lane]  : 0.f;
        ss = (lane < 8) ? red_ss[lane] : 0.f;
        #pragma unroll
        for (int o = 4; o > 0; o >>= 1) {
            s  += __shfl_xor_sync(~0u, s, o);
            ss += __shfl_xor_sync(~0u, ss, o);
        }
        if (lane == 0) { red_s[0] = s; red_ss[0] = ss; }
    }
    __syncthreads();
    float mu  = red_s[0] * (1.0f / DD);
    float var = red_ss[0] * (1.0f / DD) - mu * mu;
    float inv = rsqrtf(var + EPS_LN_);
    float4 gv = *(const float4*)&g[tid * 4];
    float4 bv = *(const float4*)&b[tid * 4];
    float* dst = &g_xn[(size_t)row * DD + (tid & ~1) * 4 + (tid & 1)];
    dst[0] = f2tff((xv.x - mu) * inv * gv.x + bv.x);
    dst[2] = f2tff((xv.y - mu) * inv * gv.y + bv.y);
    dst[4] = f2tff((xv.z - mu) * inv * gv.z + bv.z);
    dst[6] = f2tff((xv.w - mu) * inv * gv.w + bv.w);
}

// ---------------- tf32 GEMM: 128 thr, 4 warps, warp tile 64x64 -------------
// Per k-step: 16 LDS.64 feed 32 MMAs (was 12:16) -> denser tensor issue.
#define GSTR 40
#define GTILE (128 * GSTR)
__global__ __launch_bounds__(128) void gemm_tc_kernel(
    const float* __restrict__ b0, const float* __restrict__ b1,
    const float* __restrict__ b2, int mode_base, float* __restrict__ dout) {
    extern __shared__ float gsm[];
    int mode = (mode_base == 3) ? 3 : (int)blockIdx.z;
    const float* W = g_wc + (size_t)mode * DD * DD;
    const float* bias = (mode == 1) ? b1 : (mode == 2) ? b2 : b0;
    const float* Aptr = (mode < 3) ? g_xn : g_ao;

    int tid  = threadIdx.x;
    int wid  = tid >> 5;
    int lane = tid & 31;
    int g = lane >> 2, t = lane & 3;
    int wm = (wid >> 1) * 64;          // 0 or 64
    int wn = (wid & 1) * 64;           // 0 or 64
    int m0 = blockIdx.y * 128;
    int n0 = blockIdx.x * 128;
    uint32_t sbase = smem_u32(gsm);

    float acc[4][8][4];
    #pragma unroll
    for (int i = 0; i < 4; i++)
        #pragma unroll
        for (int j = 0; j < 8; j++)
            #pragma unroll
            for (int e = 0; e < 4; e++) acc[i][j][e] = 0.f;

    auto load_stage = [&](int k0, int st) {
        #pragma unroll
        for (int p = 0; p < 8; p++) {
            int slot = tid + p * 128;          // 0..1023
            int row  = slot >> 3;
            int col4 = (slot & 7) * 4;
            cp_async16(sbase + (uint32_t)((st * GTILE + row * GSTR + col4) * 4),
                       &Aptr[(size_t)(m0 + row) * DD + k0 + col4]);
            cp_async16(sbase + (uint32_t)(((2 + st) * GTILE + row * GSTR + col4) * 4),
                       &W[(size_t)(n0 + row) * DD + k0 + col4]);
        }
        cp_commit();
    };

    load_stage(0, 0);
    for (int it = 0; it < DD / 32; it++) {
        int cur = it & 1;
        cp_wait0();
        __syncthreads();
        if (it < DD / 32 - 1) load_stage((it + 1) * 32, cur ^ 1);
        const float* As = gsm + cur * GTILE;
        const float* Bs = gsm + (2 + cur) * GTILE;
        #pragma unroll
        for (int ks = 0; ks < 4; ks++) {
            int kc = ks * 8 + 2 * t;               // permuted {t, t+4} adjacent
            unsigned bf[8][2];
            #pragma unroll
            for (int n = 0; n < 8; n++) {
                float2 bb = *(const float2*)&Bs[(wn + n * 8 + g) * GSTR + kc];
                bf[n][0] = __float_as_uint(bb.x);
                bf[n][1] = __float_as_uint(bb.y);
            }
            #pragma unroll
            for (int mI = 0; mI < 4; mI++) {
                int rb = wm + mI * 16;
                float2 aA = *(const float2*)&As[(rb + g) * GSTR + kc];
                float2 aB = *(const float2*)&As[(rb + g + 8) * GSTR + kc];
                unsigned af[4] = {__float_as_uint(aA.x), __float_as_uint(aB.x),
                                  __float_as_uint(aA.y), __float_as_uint(aB.y)};
                #pragma unroll
                for (int n = 0; n < 8; n++)
                    mma_tf32(acc[mI][n], af, bf[n], acc[mI][n]);
            }
        }
    }

    #pragma unroll
    for (int mI = 0; mI < 4; mI++) {
        int r0 = m0 + wm + mI * 16 + g;
        int bi0 = r0 >> 11, t0 = r0 & (TT - 1);
        #pragma unroll
        for (int n = 0; n < 8; n++) {
            int e = n0 + wn + n * 8 + 2 * t;       // natural pair (e, e+1)
            float bb0 = bias[e], bb1 = bias[e + 1];
            float v00 = acc[mI][n][0] + bb0, v01 = acc[mI][n][1] + bb1;
            float v10 = acc[mI][n][2] + bb0, v11 = acc[mI][n][3] + bb1;
            if (mode == 3) {
                *(float2*)&dout[(size_t)r0 * DD + e] =
                    make_float2(v00 * 0.5f, v01 * 0.5f);
                *(float2*)&dout[(size_t)(r0 + 8) * DD + e] =
                    make_float2(v10 * 0.5f, v11 * 0.5f);
            } else {
                int h = e >> 6, dk = e & 63;
                size_t base0 = (((size_t)(bi0 * HH + h) * TT + t0) << 6);
                size_t base1 = base0 + (8 << 6);
                if (mode == 2) {                   // V natural, tf32-rounded
                    *(float2*)&g_v[base0 + dk] = make_float2(f2tff(v00), f2tff(v01));
                    *(float2*)&g_v[base1 + dk] = make_float2(f2tff(v10), f2tff(v11));
                } else {                           // Q,K DK-permuted scatter
                    float* C = (mode == 0) ? g_q : g_k;
                    int dkp = (dk & ~7) | perm8(dk & 7);   // pair -> dkp, dkp+2
                    C[base0 + dkp]     = v00;
                    C[base0 + dkp + 2] = v01;
                    C[base1 + dkp]     = v10;
                    C[base1 + dkp + 2] = v11;
                }
            }
        }
    }
}

// ---------------- L2 normalize (order-invariant over permuted rows) -------
__global__ __launch_bounds__(256) void l2norm_kernel() {
    int warp = (blockIdx.x * blockDim.x + threadIdx.x) >> 5;
    int lane = threadIdx.x & 31;
    float* base = (blockIdx.y == 0) ? g_q : g_k;
    float* p = base + (size_t)warp * DKK + lane * 2;
    float2 v = *(float2*)p;
    float ss = v.x * v.x + v.y * v.y;
    #pragma unroll
    for (int o = 16; o > 0; o >>= 1) ss += __shfl_xor_sync(~0u, ss, o);
    float n = sqrtf(ss);
    float inv = 1.0f / fmaxf(n, EPS_NORM_);
    v.x = f2tff(v.x * inv); v.y = f2tff(v.y * inv);
    *(float2*)p = v;
}

// ---------------- Flash attention: static softmax (R5 structure) -----------
#define ASTR 72
#define ATILE (64 * ASTR)
#define ASMEM (4 * ATILE * 4 + TT)   // bytes: K0 K1 V0 V1 + mask row
__global__ __launch_bounds__(128) void attn_tc_kernel() {
    extern __shared__ float asm_[];
    unsigned char* Msk = (unsigned char*)(asm_ + 4 * ATILE);

    int bh = blockIdx.y;
    int bi = bh >> 4;
    int h  = bh & 15;
    int qt = blockIdx.x;
    int tid = threadIdx.x;
    int wid = tid >> 5;
    int lane = tid & 31;
    int g = lane >> 2, t = lane & 3;
    int wg = wid * 16;
    uint32_t sbase = smem_u32(asm_);

    ((uint4*)Msk)[tid] = ((const uint4*)(g_cmask + bi * TT))[tid];

    // resident Q fragments (DK-permuted storage -> float2 loads)
    unsigned qa[8][4];
    {
        const float* qp0 = g_q + (((size_t)(bh * TT + qt * 64 + wg + g)) << 6);
        const float* qp1 = qp0 + (8 << 6);
        #pragma unroll
        for (int ks = 0; ks < 8; ks++) {
            float2 qA = *(const float2*)&qp0[ks * 8 + 2 * t];
            float2 qB = *(const float2*)&qp1[ks * 8 + 2 * t];
            qa[ks][0] = __float_as_uint(qA.x);
            qa[ks][1] = __float_as_uint(qB.x);
            qa[ks][2] = __float_as_uint(qA.y);
            qa[ks][3] = __float_as_uint(qB.y);
        }
    }

    float o_acc[8][4];
    #pragma unroll
    for (int n = 0; n < 8; n++)
        #pragma unroll
        for (int e = 0; e < 4; e++) o_acc[n][e] = 0.f;
    float psum0 = 0.f, psum1 = 0.f;

    const float* kbase = g_k + (((size_t)bh * TT) << 6);
    const float* vbase = g_v + (((size_t)bh * TT) << 6);

    auto load_kv = [&](int kt, int st) {
        const float* kb = kbase + ((size_t)(kt * 64) << 6);
        const float* vb = vbase + ((size_t)(kt * 64) << 6);
        #pragma unroll
        for (int p = 0; p < 8; p++) {
            int slot = tid + p * 128;
            int row  = slot >> 4;
            int col4 = (slot & 15) * 4;
            cp_async16(sbase + (uint32_t)((st * ATILE + row * ASTR + col4) * 4),
                       &kb[(row << 6) + col4]);
            cp_async16(sbase + (uint32_t)(((2 + st) * ATILE + row * ASTR + col4) * 4),
                       &vb[(row << 6) + col4]);
        }
        cp_commit();
    };

    load_kv(0, 0);
    for (int kt = 0; kt < TT / 64; kt++) {
        int cur = kt & 1;
        cp_wait0();
        __syncthreads();
        if (kt < TT / 64 - 1) load_kv(kt + 1, cur ^ 1);

        float* Ks = asm_ + cur * ATILE;
        float* Vs = asm_ + (2 + cur) * ATILE;

        // S = Q.K^T (float2 b-frags from DK-permuted K)
        float sc[8][4];
        #pragma unroll
        for (int n = 0; n < 8; n++)
            #pragma unroll
            for (int e = 0; e < 4; e++) sc[n][e] = 0.f;
        #pragma unroll
        for (int ks = 0; ks < 8; ks++) {
            int kc = ks * 8 + 2 * t;
            #pragma unroll
            for (int n = 0; n < 8; n++) {
                float2 kb2 = *(const float2*)&Ks[(n * 8 + g) * ASTR + kc];
                unsigned bf[2] = {__float_as_uint(kb2.x), __float_as_uint(kb2.y)};
                mma_tf32(sc[n], qa[ks], bf, sc[n]);
            }
        }

        // static softmax weights; masked -> 0
        const unsigned char* mrow = Msk + kt * 64;
        #pragma unroll
        for (int n = 0; n < 8; n++) {
            bool mk0 = mrow[n * 8 + 2 * t] != 0;
            bool mk1 = mrow[n * 8 + 2 * t + 1] != 0;
            sc[n][0] = mk0 ? 0.f : __expf(sc[n][0] * SCALE_);
            sc[n][1] = mk1 ? 0.f : __expf(sc[n][1] * SCALE_);
            sc[n][2] = mk0 ? 0.f : __expf(sc[n][2] * SCALE_);
            sc[n][3] = mk1 ? 0.f : __expf(sc[n][3] * SCALE_);
            psum0 += sc[n][0] + sc[n][1];
            psum1 += sc[n][2] + sc[n][3];
        }

        __syncthreads();                 // all warps done reading K[cur]
        // P (tf32) aliased over K[cur], natural key columns
        #pragma unroll
        for (int n = 0; n < 8; n++) {
            int c = n * 8 + 2 * t;
            *(float2*)&Ks[(wg + g) * ASTR + c] =
                make_float2(f2tff(sc[n][0]), f2tff(sc[n][1]));
            *(float2*)&Ks[(wg + g + 8) * ASTR + c] =
                make_float2(f2tff(sc[n][2]), f2tff(sc[n][3]));
        }
        __syncwarp();

        // O += P.V
        #pragma unroll
        for (int ks = 0; ks < 8; ks++) {
            int kc = ks * 8;
            unsigned pa[4];
            pa[0] = __float_as_uint(Ks[(wg + g) * ASTR + kc + t]);
            pa[1] = __float_as_uint(Ks[(wg + g + 8) * ASTR + kc + t]);
            pa[2] = __float_as_uint(Ks[(wg + g) * ASTR + kc + t + 4]);
            pa[3] = __float_as_uint(Ks[(wg + g + 8) * ASTR + kc + t + 4]);
            #pragma unroll
            for (int n = 0; n < 8; n++) {
                unsigned bf[2];
                bf[0] = __float_as_uint(Vs[(kc + t) * ASTR + n * 8 + g]);
                bf[1] = __float_as_uint(Vs[(kc + t + 4) * ASTR + n * 8 + g]);
                mma_tf32(o_acc[n], pa, bf, o_acc[n]);
            }
        }
    }

    psum0 += __shfl_xor_sync(~0u, psum0, 1);
    psum0 += __shfl_xor_sync(~0u, psum0, 2);
    psum1 += __shfl_xor_sync(~0u, psum1, 1);
    psum1 += __shfl_xor_sync(~0u, psum1, 2);
    float inv0 = 1.0f / psum0;
    float inv1 = 1.0f / psum1;
    int tq0 = qt * 64 + wg + g;
    float* ob0 = g_ao + ((size_t)bi * TT + tq0) * DD + h * 64;
    float* ob1 = ob0 + 8 * DD;
    #pragma unroll
    for (int n = 0; n < 8; n++) {
        int p0 = n * 8 + perm8(2 * t);            // D-perm for O-GEMM feed
        ob0[p0]     = f2tff(o_acc[n][0] * inv0);
        ob0[p0 + 2] = f2tff(o_acc[n][1] * inv0);
        ob1[p0]     = f2tff(o_acc[n][2] * inv1);
        ob1[p0 + 2] = f2tff(o_acc[n][3] * inv1);
    }
}

// ---------------- launch ----------------
extern "C" void kernel_launch(void* const* d_in, const int* in_sizes, int n_in,
                              void* d_out, int out_size) {
    const float* x    = (const float*)d_in[0];
    const void*  mask = d_in[1];
    const float* wq = (const float*)d_in[2];
    const float* bq = (const float*)d_in[3];
    const float* wk = (const float*)d_in[4];
    const float* bk = (const float*)d_in[5];
    const float* wv = (const float*)d_in[6];
    const float* bv = (const float*)d_in[7];
    const float* wo = (const float*)d_in[8];
    const float* bo = (const float*)d_in[9];
    const float* ln_g = (const float*)d_in[10];
    const float* ln_b = (const float*)d_in[11];
    float* out = (float*)d_out;

    const int gemm_smem = 4 * GTILE * 4;          // 81920 B
    const int attn_smem = ASMEM;                  // 75776 B
    cudaFuncSetAttribute(gemm_tc_kernel,
        cudaFuncAttributeMaxDynamicSharedMemorySize, gemm_smem);
    cudaFuncSetAttribute(attn_tc_kernel,
        cudaFuncAttributeMaxDynamicSharedMemorySize, attn_smem);

    detect_mask_kernel<<<1, 256>>>((const unsigned char*)mask);
    convert_mask_kernel<<<(BB * TT + 255) / 256, 256>>>(mask);
    wconv_kernel<<<dim3(DD * DD / 1024, 4), 256>>>(wq, wk, wv, wo);
    ln_kernel<<<BB * TT, 256>>>(x, ln_g, ln_b);

    dim3 qkv_grid(DD / 128, (BB * TT) / 128, 3);
    gemm_tc_kernel<<<qkv_grid, 128, gemm_smem>>>(bq, bk, bv, 0, nullptr);

    dim3 l2grid((BB * HH * TT) / 8, 2);
    l2norm_kernel<<<l2grid, 256>>>();

    dim3 agrid(TT / 64, BB * HH);                 // (32, 64)
    attn_tc_kernel<<<agrid, 128, attn_smem>>>();

    dim3 ogrid(DD / 128, (BB * TT) / 128, 1);
    gemm_tc_kernel<<<ogrid, 128, gemm_smem>>>(bo, nullptr, nullptr, 3, out);
}

// round 8
// speedup vs baseline: 1.5927x; 1.0174x over previous
#include <cuda_runtime.h>
#include <cstdint>

#define BB 4
#define TT 2048
#define DD 1024
#define HH 16
#define DKK 64
#define SCALE_ 0.125f
#define EPS_LN_ 1e-5f
#define EPS_NORM_ 1e-8f

// within-8 column permutation: natural col c -> stored position perm8(c)
// order [0,4,1,5,2,6,3,7]; perm8(t)=2t, perm8(t+4)=2t+1 for t<4
__host__ __device__ __forceinline__ constexpr int perm8(int c) {
    return ((c & 3) << 1) | ((c >> 2) & 1);
}

// ---------------- scratch ----------------
__device__ float g_xn[BB * TT * DD];           // LN output, D-permuted
__device__ float g_q[BB * HH * TT * DKK];      // DK-permuted
__device__ float g_k[BB * HH * TT * DKK];      // DK-permuted
__device__ float g_v[BB * HH * TT * DKK];      // block-transposed [BH][T/64][DK][64key-perm]
__device__ float g_ao[BB * TT * DD];           // attention out, D-permuted
__device__ float g_wc[4 * DD * DD];            // tf32 weights, k-dim permuted
__device__ unsigned char g_cmask[BB * TT];
__device__ int g_flags[3];

// ---------------- helpers ----------------
__device__ __forceinline__ unsigned f2tf(float x) {
    unsigned r;
    asm("cvt.rna.tf32.f32 %0, %1;" : "=r"(r) : "f"(x));
    return r;
}
__device__ __forceinline__ float f2tff(float x) { return __uint_as_float(f2tf(x)); }

__device__ __forceinline__ void mma_tf32(float* d, const unsigned* a,
                                         const unsigned* b, const float* c) {
    asm volatile(
        "mma.sync.aligned.m16n8k8.row.col.f32.tf32.tf32.f32 "
        "{%0,%1,%2,%3}, {%4,%5,%6,%7}, {%8,%9}, {%10,%11,%12,%13};"
        : "=f"(d[0]), "=f"(d[1]), "=f"(d[2]), "=f"(d[3])
        : "r"(a[0]), "r"(a[1]), "r"(a[2]), "r"(a[3]),
          "r"(b[0]), "r"(b[1]),
          "f"(c[0]), "f"(c[1]), "f"(c[2]), "f"(c[3]));
}
__device__ __forceinline__ void cp_async16(uint32_t saddr, const void* gptr) {
    asm volatile("cp.async.cg.shared.global [%0], [%1], 16;\n" :: "r"(saddr), "l"(gptr));
}
__device__ __forceinline__ void cp_commit() { asm volatile("cp.async.commit_group;\n" ::); }
__device__ __forceinline__ void cp_wait0()  { asm volatile("cp.async.wait_group 0;\n" ::); }
__device__ __forceinline__ uint32_t smem_u32(const void* p) {
    return (uint32_t)__cvta_generic_to_shared(p);
}

// ---------------- mask detection / canonicalization ----------------
__global__ void detect_mask_kernel(const unsigned char* __restrict__ m) {
    if (threadIdx.x == 0) { g_flags[0] = 0; g_flags[1] = 0; g_flags[2] = 0; }
    __syncthreads();
    int a = 0, bhi = 0, c = 0;
    for (int i = threadIdx.x; i < BB * TT; i += blockDim.x) {
        unsigned char v = m[i];
        if (v) {
            int r = i & 3;
            if (r == 0) a = 1;
            else if (r == 1) c = 1;
            else bhi = 1;
        }
    }
    if (a)   atomicOr(&g_flags[0], 1);
    if (bhi) atomicOr(&g_flags[1], 1);
    if (c)   atomicOr(&g_flags[2], 1);
}
__global__ void convert_mask_kernel(const void* __restrict__ m) {
    int i = blockIdx.x * blockDim.x + threadIdx.x;
    if (i >= BB * TT) return;
    int A = g_flags[0], Bf = g_flags[1], C = g_flags[2];
    unsigned char out;
    if (A && !Bf && !C)      out = (((const int*)m)[i] != 0);
    else if (!A && Bf)       out = (((const float*)m)[i] != 0.0f);
    else                     out = (((const unsigned char*)m)[i] != 0);
    g_cmask[i] = out;
}

// ---------------- weight conversion: tf32 round + k-dim perm ----------------
__global__ __launch_bounds__(256) void wconv_kernel(
    const float* __restrict__ w0, const float* __restrict__ w1,
    const float* __restrict__ w2, const float* __restrict__ w3) {
    const float* src = (blockIdx.y == 0) ? w0 : (blockIdx.y == 1) ? w1
                     : (blockIdx.y == 2) ? w2 : w3;
    float* dst = g_wc + (size_t)blockIdx.y * DD * DD;
    size_t i = ((size_t)blockIdx.x * 256 + threadIdx.x) * 4;
    float4 v = *(const float4*)&src[i];
    size_t base = (i & ~(size_t)7) + ((i & 4) >> 2);
    dst[base + 0] = f2tff(v.x);
    dst[base + 2] = f2tff(v.y);
    dst[base + 4] = f2tff(v.z);
    dst[base + 6] = f2tff(v.w);
}

// ---------------- LayerNorm: tf32 round + D-perm ----------------
__global__ __launch_bounds__(256) void ln_kernel(
    const float* __restrict__ x, const float* __restrict__ g,
    const float* __restrict__ b) {
    __shared__ float red_s[8], red_ss[8];
    int row = blockIdx.x;
    int tid = threadIdx.x;
    const float* xr = x + (size_t)row * DD;
    float4 xv = *(const float4*)&xr[tid * 4];
    float s  = xv.x + xv.y + xv.z + xv.w;
    float ss = xv.x*xv.x + xv.y*xv.y + xv.z*xv.z + xv.w*xv.w;
    #pragma unroll
    for (int o = 16; o > 0; o >>= 1) {
        s  += __shfl_xor_sync(~0u, s, o);
        ss += __shfl_xor_sync(~0u, ss, o);
    }
    int warp = tid >> 5, lane = tid & 31;
    if (lane == 0) { red_s[warp] = s; red_ss[warp] = ss; }
    __syncthreads();
    if (warp == 0) {
        s  = (lane < 8) ? red_s[lane]  : 0.f;
        ss = (lane < 8) ? red_ss[lane] : 0.f;
        #pragma unroll
        for (int o = 4; o > 0; o >>= 1) {
            s  += __shfl_xor_sync(~0u, s, o);
            ss += __shfl_xor_sync(~0u, ss, o);
        }
        if (lane == 0) { red_s[0] = s; red_ss[0] = ss; }
    }
    __syncthreads();
    float mu  = red_s[0] * (1.0f / DD);
    float var = red_ss[0] * (1.0f / DD) - mu * mu;
    float inv = rsqrtf(var + EPS_LN_);
    float4 gv = *(const float4*)&g[tid * 4];
    float4 bv = *(const float4*)&b[tid * 4];
    float* dst = &g_xn[(size_t)row * DD + (tid & ~1) * 4 + (tid & 1)];
    dst[0] = f2tff((xv.x - mu) * inv * gv.x + bv.x);
    dst[2] = f2tff((xv.y - mu) * inv * gv.y + bv.y);
    dst[4] = f2tff((xv.z - mu) * inv * gv.z + bv.z);
    dst[6] = f2tff((xv.w - mu) * inv * gv.w + bv.w);
}

// ---------------- tf32 GEMM (R5 config: 256 thr, warp tile 64x32) ----------
#define GSTR 40
#define GTILE (128 * GSTR)
__global__ __launch_bounds__(256) void gemm_tc_kernel(
    const float* __restrict__ b0, const float* __restrict__ b1,
    const float* __restrict__ b2, int mode_base, float* __restrict__ dout) {
    extern __shared__ float gsm[];
    int mode = (mode_base == 3) ? 3 : (int)blockIdx.z;
    const float* W = g_wc + (size_t)mode * DD * DD;
    const float* bias = (mode == 1) ? b1 : (mode == 2) ? b2 : b0;
    const float* Aptr = (mode < 3) ? g_xn : g_ao;

    int tid  = threadIdx.x;
    int wid  = tid >> 5;
    int lane = tid & 31;
    int g = lane >> 2, t = lane & 3;
    int wm = (wid >> 2) * 64;
    int wn = (wid & 3) * 32;
    int m0 = blockIdx.y * 128;
    int n0 = blockIdx.x * 128;
    uint32_t sbase = smem_u32(gsm);

    float acc[4][4][4];
    #pragma unroll
    for (int i = 0; i < 4; i++)
        #pragma unroll
        for (int j = 0; j < 4; j++)
            #pragma unroll
            for (int e = 0; e < 4; e++) acc[i][j][e] = 0.f;

    auto load_stage = [&](int k0, int st) {
        #pragma unroll
        for (int p = 0; p < 4; p++) {
            int slot = tid + p * 256;
            int row  = slot >> 3;
            int col4 = (slot & 7) * 4;
            cp_async16(sbase + (uint32_t)((st * GTILE + row * GSTR + col4) * 4),
                       &Aptr[(size_t)(m0 + row) * DD + k0 + col4]);
            cp_async16(sbase + (uint32_t)(((2 + st) * GTILE + row * GSTR + col4) * 4),
                       &W[(size_t)(n0 + row) * DD + k0 + col4]);
        }
        cp_commit();
    };

    load_stage(0, 0);
    for (int it = 0; it < DD / 32; it++) {
        int cur = it & 1;
        cp_wait0();
        __syncthreads();
        if (it < DD / 32 - 1) load_stage((it + 1) * 32, cur ^ 1);
        const float* As = gsm + cur * GTILE;
        const float* Bs = gsm + (2 + cur) * GTILE;
        #pragma unroll
        for (int ks = 0; ks < 4; ks++) {
            int kc = ks * 8 + 2 * t;               // permuted {t, t+4} adjacent
            unsigned bf[4][2];
            #pragma unroll
            for (int n = 0; n < 4; n++) {
                float2 bb = *(const float2*)&Bs[(wn + n * 8 + g) * GSTR + kc];
                bf[n][0] = __float_as_uint(bb.x);
                bf[n][1] = __float_as_uint(bb.y);
            }
            #pragma unroll
            for (int mI = 0; mI < 4; mI++) {
                int rb = wm + mI * 16;
                float2 aA = *(const float2*)&As[(rb + g) * GSTR + kc];
                float2 aB = *(const float2*)&As[(rb + g + 8) * GSTR + kc];
                unsigned af[4] = {__float_as_uint(aA.x), __float_as_uint(aB.x),
                                  __float_as_uint(aA.y), __float_as_uint(aB.y)};
                #pragma unroll
                for (int n = 0; n < 4; n++)
                    mma_tf32(acc[mI][n], af, bf[n], acc[mI][n]);
            }
        }
    }

    #pragma unroll
    for (int mI = 0; mI < 4; mI++) {
        int r0 = m0 + wm + mI * 16 + g;
        int bi0 = r0 >> 11, t0 = r0 & (TT - 1);
        #pragma unroll
        for (int n = 0; n < 4; n++) {
            int e = n0 + wn + n * 8 + 2 * t;       // natural pair (e, e+1)
            float bb0 = bias[e], bb1 = bias[e + 1];
            float v00 = acc[mI][n][0] + bb0, v01 = acc[mI][n][1] + bb1;
            float v10 = acc[mI][n][2] + bb0, v11 = acc[mI][n][3] + bb1;
            if (mode == 3) {
                *(float2*)&dout[(size_t)r0 * DD + e] =
                    make_float2(v00 * 0.5f, v01 * 0.5f);
                *(float2*)&dout[(size_t)(r0 + 8) * DD + e] =
                    make_float2(v10 * 0.5f, v11 * 0.5f);
            } else {
                int h = e >> 6, dk = e & 63;
                if (mode == 2) {
                    // V block-transposed: [BH][T/64][DK][64key-perm]
                    int kt0 = t0 >> 6, ik = t0 & 63;
                    int pk = (ik & ~7) | perm8(ik & 7);   // row+8 -> pk+8
                    float* vb = g_v +
                        ((((size_t)(bi0 * HH + h) * (TT / 64) + kt0) * DKK + dk) << 6);
                    vb[pk]          = f2tff(v00);
                    vb[64 + pk]     = f2tff(v01);     // dk+1
                    vb[pk + 8]      = f2tff(v10);     // key t0+8
                    vb[64 + pk + 8] = f2tff(v11);
                } else {                           // Q,K DK-permuted scatter
                    float* C = (mode == 0) ? g_q : g_k;
                    int dkp = (dk & ~7) | perm8(dk & 7);   // pair -> dkp, dkp+2
                    size_t base0 = (((size_t)(bi0 * HH + h) * TT + t0) << 6);
                    size_t base1 = base0 + (8 << 6);
                    C[base0 + dkp]     = v00;
                    C[base0 + dkp + 2] = v01;
                    C[base1 + dkp]     = v10;
                    C[base1 + dkp + 2] = v11;
                }
            }
        }
    }
}

// ---------------- L2 normalize (order-invariant over permuted rows) -------
__global__ __launch_bounds__(256) void l2norm_kernel() {
    int warp = (blockIdx.x * blockDim.x + threadIdx.x) >> 5;
    int lane = threadIdx.x & 31;
    float* base = (blockIdx.y == 0) ? g_q : g_k;
    float* p = base + (size_t)warp * DKK + lane * 2;
    float2 v = *(float2*)p;
    float ss = v.x * v.x + v.y * v.y;
    #pragma unroll
    for (int o = 16; o > 0; o >>= 1) ss += __shfl_xor_sync(~0u, ss, o);
    float n = sqrtf(ss);
    float inv = 1.0f / fmaxf(n, EPS_NORM_);
    v.x = f2tff(v.x * inv); v.y = f2tff(v.y * inv);
    *(float2*)p = v;
}

// ---------------- Flash attention: static softmax, Vt tiles ----------------
#define ASTR 72
#define ATILE (64 * ASTR)
#define ASMEM (4 * ATILE * 4 + TT)   // bytes: K0 K1 Vt0 Vt1 + mask row
__global__ __launch_bounds__(128) void attn_tc_kernel() {
    extern __shared__ float asm_[];
    unsigned char* Msk = (unsigned char*)(asm_ + 4 * ATILE);

    int bh = blockIdx.y;
    int bi = bh >> 4;
    int h  = bh & 15;
    int qt = blockIdx.x;
    int tid = threadIdx.x;
    int wid = tid >> 5;
    int lane = tid & 31;
    int g = lane >> 2, t = lane & 3;
    int wg = wid * 16;
    uint32_t sbase = smem_u32(asm_);

    ((uint4*)Msk)[tid] = ((const uint4*)(g_cmask + bi * TT))[tid];

    // resident Q fragments (DK-permuted storage -> float2 loads)
    unsigned qa[8][4];
    {
        const float* qp0 = g_q + (((size_t)(bh * TT + qt * 64 + wg + g)) << 6);
        const float* qp1 = qp0 + (8 << 6);
        #pragma unroll
        for (int ks = 0; ks < 8; ks++) {
            float2 qA = *(const float2*)&qp0[ks * 8 + 2 * t];
            float2 qB = *(const float2*)&qp1[ks * 8 + 2 * t];
            qa[ks][0] = __float_as_uint(qA.x);
            qa[ks][1] = __float_as_uint(qB.x);
            qa[ks][2] = __float_as_uint(qA.y);
            qa[ks][3] = __float_as_uint(qB.y);
        }
    }

    float o_acc[8][4];
    #pragma unroll
    for (int n = 0; n < 8; n++)
        #pragma unroll
        for (int e = 0; e < 4; e++) o_acc[n][e] = 0.f;
    float psum0 = 0.f, psum1 = 0.f;

    const float* kbase = g_k + (((size_t)bh * TT) << 6);
    const float* vbase = g_v + (((size_t)bh * TT) << 6);   // tile kt at (kt*64)<<6

    auto load_kv = [&](int kt, int st) {
        const float* kb = kbase + ((size_t)(kt * 64) << 6);
        const float* vb = vbase + ((size_t)(kt * 64) << 6); // Vt tile: row=dk, col=key
        #pragma unroll
        for (int p = 0; p < 8; p++) {
            int slot = tid + p * 128;
            int row  = slot >> 4;
            int col4 = (slot & 15) * 4;
            cp_async16(sbase + (uint32_t)((st * ATILE + row * ASTR + col4) * 4),
                       &kb[(row << 6) + col4]);
            cp_async16(sbase + (uint32_t)(((2 + st) * ATILE + row * ASTR + col4) * 4),
                       &vb[(row << 6) + col4]);
        }
        cp_commit();
    };

    load_kv(0, 0);
    for (int kt = 0; kt < TT / 64; kt++) {
        int cur = kt & 1;
        cp_wait0();
        __syncthreads();
        if (kt < TT / 64 - 1) load_kv(kt + 1, cur ^ 1);

        float* Ks = asm_ + cur * ATILE;
        float* Vs = asm_ + (2 + cur) * ATILE;    // Vt: [dk][key-perm]

        // S = Q.K^T (float2 b-frags from DK-permuted K)
        float sc[8][4];
        #pragma unroll
        for (int n = 0; n < 8; n++)
            #pragma unroll
            for (int e = 0; e < 4; e++) sc[n][e] = 0.f;
        #pragma unroll
        for (int ks = 0; ks < 8; ks++) {
            int kc = ks * 8 + 2 * t;
            #pragma unroll
            for (int n = 0; n < 8; n++) {
                float2 kb2 = *(const float2*)&Ks[(n * 8 + g) * ASTR + kc];
                unsigned bf[2] = {__float_as_uint(kb2.x), __float_as_uint(kb2.y)};
                mma_tf32(sc[n], qa[ks], bf, sc[n]);
            }
        }

        // static softmax weights; masked -> 0
        const unsigned char* mrow = Msk + kt * 64;
        #pragma unroll
        for (int n = 0; n < 8; n++) {
            bool mk0 = mrow[n * 8 + 2 * t] != 0;
            bool mk1 = mrow[n * 8 + 2 * t + 1] != 0;
            sc[n][0] = mk0 ? 0.f : __expf(sc[n][0] * SCALE_);
            sc[n][1] = mk1 ? 0.f : __expf(sc[n][1] * SCALE_);
            sc[n][2] = mk0 ? 0.f : __expf(sc[n][2] * SCALE_);
            sc[n][3] = mk1 ? 0.f : __expf(sc[n][3] * SCALE_);
            psum0 += sc[n][0] + sc[n][1];
            psum1 += sc[n][2] + sc[n][3];
        }

        __syncthreads();                 // all warps done reading K[cur]
        // P (tf32) aliased over K[cur], KEY-PERMUTED columns
        #pragma unroll
        for (int n = 0; n < 8; n++) {
            int p0 = n * 8 + perm8(2 * t);        // key 2t -> p0, key 2t+1 -> p0+2
            Ks[(wg + g) * ASTR + p0]         = f2tff(sc[n][0]);
            Ks[(wg + g) * ASTR + p0 + 2]     = f2tff(sc[n][1]);
            Ks[(wg + g + 8) * ASTR + p0]     = f2tff(sc[n][2]);
            Ks[(wg + g + 8) * ASTR + p0 + 2] = f2tff(sc[n][3]);
        }
        __syncwarp();

        // O += P.V : all-float2 fragment feeds
        #pragma unroll
        for (int ks = 0; ks < 8; ks++) {
            int kc = ks * 8 + 2 * t;              // perm pos of keys {t, t+4}
            float2 pA = *(const float2*)&Ks[(wg + g) * ASTR + kc];
            float2 pB = *(const float2*)&Ks[(wg + g + 8) * ASTR + kc];
            unsigned pa[4] = {__float_as_uint(pA.x), __float_as_uint(pB.x),
                              __float_as_uint(pA.y), __float_as_uint(pB.y)};
            #pragma unroll
            for (int n = 0; n < 8; n++) {
                float2 vb2 = *(const float2*)&Vs[(n * 8 + g) * ASTR + kc];
                unsigned bf[2] = {__float_as_uint(vb2.x), __float_as_uint(vb2.y)};
                mma_tf32(o_acc[n], pa, bf, o_acc[n]);
            }
        }
    }

    psum0 += __shfl_xor_sync(~0u, psum0, 1);
    psum0 += __shfl_xor_sync(~0u, psum0, 2);
    psum1 += __shfl_xor_sync(~0u, psum1, 1);
    psum1 += __shfl_xor_sync(~0u, psum1, 2);
    float inv0 = 1.0f / psum0;
    float inv1 = 1.0f / psum1;
    int tq0 = qt * 64 + wg + g;
    float* ob0 = g_ao + ((size_t)bi * TT + tq0) * DD + h * 64;
    float* ob1 = ob0 + 8 * DD;
    #pragma unroll
    for (int n = 0; n < 8; n++) {
        int p0 = n * 8 + perm8(2 * t);            // D-perm for O-GEMM feed
        ob0[p0]     = f2tff(o_acc[n][0] * inv0);
        ob0[p0 + 2] = f2tff(o_acc[n][1] * inv0);
        ob1[p0]     = f2tff(o_acc[n][2] * inv1);
        ob1[p0 + 2] = f2tff(o_acc[n][3] * inv1);
    }
}

// ---------------- launch ----------------
extern "C" void kernel_launch(void* const* d_in, const int* in_sizes, int n_in,
                              void* d_out, int out_size) {
    const float* x    = (const float*)d_in[0];
    const void*  mask = d_in[1];
    const float* wq = (const float*)d_in[2];
    const float* bq = (const float*)d_in[3];
    const float* wk = (const float*)d_in[4];
    const float* bk = (const float*)d_in[5];
    const float* wv = (const float*)d_in[6];
    const float* bv = (const float*)d_in[7];
    const float* wo = (const float*)d_in[8];
    const float* bo = (const float*)d_in[9];
    const float* ln_g = (const float*)d_in[10];
    const float* ln_b = (const float*)d_in[11];
    float* out = (float*)d_out;

    const int gemm_smem = 4 * GTILE * 4;          // 81920 B
    const int attn_smem = ASMEM;                  // 75776 B
    cudaFuncSetAttribute(gemm_tc_kernel,
        cudaFuncAttributeMaxDynamicSharedMemorySize, gemm_smem);
    cudaFuncSetAttribute(attn_tc_kernel,
        cudaFuncAttributeMaxDynamicSharedMemorySize, attn_smem);

    detect_mask_kernel<<<1, 256>>>((const unsigned char*)mask);
    convert_mask_kernel<<<(BB * TT + 255) / 256, 256>>>(mask);
    wconv_kernel<<<dim3(DD * DD / 1024, 4), 256>>>(wq, wk, wv, wo);
    ln_kernel<<<BB * TT, 256>>>(x, ln_g, ln_b);

    dim3 qkv_grid(DD / 128, (BB * TT) / 128, 3);
    gemm_tc_kernel<<<qkv_grid, 256, gemm_smem>>>(bq, bk, bv, 0, nullptr);

    dim3 l2grid((BB * HH * TT) / 8, 2);
    l2norm_kernel<<<l2grid, 256>>>();

    dim3 agrid(TT / 64, BB * HH);                 // (32, 64)
    attn_tc_kernel<<<agrid, 128, attn_smem>>>();

    dim3 ogrid(DD / 128, (BB * TT) / 128, 1);
    gemm_tc_kernel<<<ogrid, 256, gemm_smem>>>(bo, nullptr, nullptr, 3, out);
}

// round 10
// speedup vs baseline: 1.8359x; 1.1527x over previous
#include <cuda_runtime.h>
#include <cuda_bf16.h>
#include <cstdint>

#define BB 4
#define TT 2048
#define DD 1024
#define HH 16
#define DKK 64
#define SCALE_ 0.125f
#define EPS_LN_ 1e-5f
#define EPS_NORM_ 1e-8f

// tf32 within-8 perm: [0,4,1,5,2,6,3,7]; perm8(t)=2t, perm8(t+4)=2t+1
__host__ __device__ __forceinline__ constexpr int perm8(int c) {
    return ((c & 3) << 1) | ((c >> 2) & 1);
}
// bf16 within-16 perm: natural c -> 4*((c>>1)&3) + 2*((c>>3)&1) + (c&1)
// so k-pairs {2t,2t+1}->{4t,4t+1} and {2t+8,2t+9}->{4t+2,4t+3} (one b64 load)
__host__ __device__ __forceinline__ constexpr int perm16(int c) {
    return (((c >> 1) & 3) << 2) + (((c >> 3) & 1) << 1) + (c & 1);
}

// ---------------- scratch ----------------
__device__ float g_xn[BB * TT * DD];              // LN out, tf32, D-perm8 (V-GEMM)
__device__ __nv_bfloat16 g_xnh[BB * TT * DD];     // LN out, bf16, D-perm16 (Q/K GEMM)
__device__ __nv_bfloat16 g_qh[BB * HH * TT * DKK];// Q bf16, DK-perm16
__device__ __nv_bfloat16 g_kh[BB * HH * TT * DKK];// K bf16, DK-perm16
__device__ float g_v[BB * HH * TT * DKK];         // V tf32, block-transposed [BH][T/64][DK][64kp]
__device__ float g_ao[BB * TT * DD];              // attn out, tf32, D-perm8
__device__ float g_wc[2 * DD * DD];               // wv, wo  tf32 perm8
__device__ __nv_bfloat16 g_wch[2 * DD * DD];      // wq, wk  bf16 perm16
__device__ unsigned char g_cmask[BB * TT];
__device__ int g_flags[3];

// ---------------- helpers ----------------
__device__ __forceinline__ unsigned f2tf(float x) {
    unsigned r;
    asm("cvt.rna.tf32.f32 %0, %1;" : "=r"(r) : "f"(x));
    return r;
}
__device__ __forceinline__ float f2tff(float x) { return __uint_as_float(f2tf(x)); }

__device__ __forceinline__ void mma_tf32(float* d, const unsigned* a,
                                         const unsigned* b, const float* c) {
    asm volatile(
        "mma.sync.aligned.m16n8k8.row.col.f32.tf32.tf32.f32 "
        "{%0,%1,%2,%3}, {%4,%5,%6,%7}, {%8,%9}, {%10,%11,%12,%13};"
        : "=f"(d[0]), "=f"(d[1]), "=f"(d[2]), "=f"(d[3])
        : "r"(a[0]), "r"(a[1]), "r"(a[2]), "r"(a[3]),
          "r"(b[0]), "r"(b[1]),
          "f"(c[0]), "f"(c[1]), "f"(c[2]), "f"(c[3]));
}
__device__ __forceinline__ void mma_bf16(float* d, const unsigned* a,
                                         const unsigned* b, const float* c) {
    asm volatile(
        "mma.sync.aligned.m16n8k16.row.col.f32.bf16.bf16.f32 "
        "{%0,%1,%2,%3}, {%4,%5,%6,%7}, {%8,%9}, {%10,%11,%12,%13};"
        : "=f"(d[0]), "=f"(d[1]), "=f"(d[2]), "=f"(d[3])
        : "r"(a[0]), "r"(a[1]), "r"(a[2]), "r"(a[3]),
          "r"(b[0]), "r"(b[1]),
          "f"(c[0]), "f"(c[1]), "f"(c[2]), "f"(c[3]));
}
__device__ __forceinline__ void cp_async16(uint32_t saddr, const void* gptr) {
    asm volatile("cp.async.cg.shared.global [%0], [%1], 16;\n" :: "r"(saddr), "l"(gptr));
}
__device__ __forceinline__ void cp_commit() { asm volatile("cp.async.commit_group;\n" ::); }
__device__ __forceinline__ void cp_wait0()  { asm volatile("cp.async.wait_group 0;\n" ::); }
__device__ __forceinline__ uint32_t smem_u32(const void* p) {
    return (uint32_t)__cvta_generic_to_shared(p);
}

// ---------------- mask detection / canonicalization ----------------
__global__ void detect_mask_kernel(const unsigned char* __restrict__ m) {
    if (threadIdx.x == 0) { g_flags[0] = 0; g_flags[1] = 0; g_flags[2] = 0; }
    __syncthreads();
    int a = 0, bhi = 0, c = 0;
    for (int i = threadIdx.x; i < BB * TT; i += blockDim.x) {
        unsigned char v = m[i];
        if (v) {
            int r = i & 3;
            if (r == 0) a = 1;
            else if (r == 1) c = 1;
            else bhi = 1;
        }
    }
    if (a)   atomicOr(&g_flags[0], 1);
    if (bhi) atomicOr(&g_flags[1], 1);
    if (c)   atomicOr(&g_flags[2], 1);
}
__global__ void convert_mask_kernel(const void* __restrict__ m) {
    int i = blockIdx.x * blockDim.x + threadIdx.x;
    if (i >= BB * TT) return;
    int A = g_flags[0], Bf = g_flags[1], C = g_flags[2];
    unsigned char out;
    if (A && !Bf && !C)      out = (((const int*)m)[i] != 0);
    else if (!A && Bf)       out = (((const float*)m)[i] != 0.0f);
    else                     out = (((const unsigned char*)m)[i] != 0);
    g_cmask[i] = out;
}

// ---------------- weight conversion ----------------
// y=0,1: wq,wk -> bf16 perm16.  y=2,3: wv,wo -> tf32 perm8.
__global__ __launch_bounds__(256) void wconv_kernel(
    const float* __restrict__ w0, const float* __restrict__ w1,
    const float* __restrict__ w2, const float* __restrict__ w3) {
    int y = blockIdx.y;
    const float* src = (y == 0) ? w0 : (y == 1) ? w1 : (y == 2) ? w2 : w3;
    size_t i = ((size_t)blockIdx.x * 256 + threadIdx.x) * 4;
    float4 v = *(const float4*)&src[i];
    if (y < 2) {
        __nv_bfloat16* dst = g_wch + (size_t)y * DD * DD;
        int r = (int)(i & 15);                       // 0,4,8,12
        int p0 = (((r >> 1) & 3) << 2) + (((r >> 3) & 1) << 1);
        size_t b16 = i & ~(size_t)15;
        *(__nv_bfloat162*)&dst[b16 + p0]     = __floats2bfloat162_rn(v.x, v.y);
        *(__nv_bfloat162*)&dst[b16 + p0 + 4] = __floats2bfloat162_rn(v.z, v.w);
    } else {
        float* dst = g_wc + (size_t)(y - 2) * DD * DD;
        size_t base = (i & ~(size_t)7) + ((i & 4) >> 2);
        dst[base + 0] = f2tff(v.x);
        dst[base + 2] = f2tff(v.y);
        dst[base + 4] = f2tff(v.z);
        dst[base + 6] = f2tff(v.w);
    }
}

// ---------------- LayerNorm: tf32 perm8 + bf16 perm16 outputs ----------------
__global__ __launch_bounds__(256) void ln_kernel(
    const float* __restrict__ x, const float* __restrict__ g,
    const float* __restrict__ b) {
    __shared__ float red_s[8], red_ss[8];
    int row = blockIdx.x;
    int tid = threadIdx.x;
    const float* xr = x + (size_t)row * DD;
    float4 xv = *(const float4*)&xr[tid * 4];
    float s  = xv.x + xv.y + xv.z + xv.w;
    float ss = xv.x*xv.x + xv.y*xv.y + xv.z*xv.z + xv.w*xv.w;
    #pragma unroll
    for (int o = 16; o > 0; o >>= 1) {
        s  += __shfl_xor_sync(~0u, s, o);
        ss += __shfl_xor_sync(~0u, ss, o);
    }
    int warp = tid >> 5, lane = tid & 31;
    if (lane == 0) { red_s[warp] = s; red_ss[warp] = ss; }
    __syncthreads();
    if (warp == 0) {
        s  = (lane < 8) ? red_s[lane]  : 0.f;
        ss = (lane < 8) ? red_ss[lane] : 0.f;
        #pragma unroll
        for (int o = 4; o > 0; o >>= 1) {
            s  += __shfl_xor_sync(~0u, s, o);
            ss += __shfl_xor_sync(~0u, ss, o);
        }
        if (lane == 0) { red_s[0] = s; red_ss[0] = ss; }
    }
    __syncthreads();
    float mu  = red_s[0] * (1.0f / DD);
    float var = red_ss[0] * (1.0f / DD) - mu * mu;
    float inv = rsqrtf(var + EPS_LN_);
    float4 gv = *(const float4*)&g[tid * 4];
    float4 bv = *(const float4*)&b[tid * 4];
    float y0 = (xv.x - mu) * inv * gv.x + bv.x;
    float y1 = (xv.y - mu) * inv * gv.y + bv.y;
    float y2 = (xv.z - mu) * inv * gv.z + bv.z;
    float y3 = (xv.w - mu) * inv * gv.w + bv.w;
    // tf32 perm8 (for V-GEMM)
    float* dst = &g_xn[(size_t)row * DD + (tid & ~1) * 4 + (tid & 1)];
    dst[0] = f2tff(y0); dst[2] = f2tff(y1);
    dst[4] = f2tff(y2); dst[6] = f2tff(y3);
    // bf16 perm16 (for Q/K GEMM)
    int c0 = tid * 4;
    int r = c0 & 15;                                 // 0,4,8,12
    int p0 = (((r >> 1) & 3) << 2) + (((r >> 3) & 1) << 1);
    __nv_bfloat16* hd = g_xnh + (size_t)row * DD + (c0 & ~15);
    *(__nv_bfloat162*)&hd[p0]     = __floats2bfloat162_rn(y0, y1);
    *(__nv_bfloat162*)&hd[p0 + 4] = __floats2bfloat162_rn(y2, y3);
}

// ---------------- bf16 GEMM for Q,K: 256 thr, warp tile 64x32 --------------
#define HSTR 48                     // halves per smem row (96B; k-chunk is 32 halves)
#define HTILE (128 * HSTR)          // halves per tile
__global__ __launch_bounds__(256) void gemm_qk_kernel(
    const float* __restrict__ bq, const float* __restrict__ bk) {
    extern __shared__ __nv_bfloat16 hsm[];
    int mode = blockIdx.z;                           // 0=Q, 1=K
    const __nv_bfloat16* W = g_wch + (size_t)mode * DD * DD;
    const float* bias = mode ? bk : bq;
    __nv_bfloat16* C = mode ? g_kh : g_qh;

    int tid  = threadIdx.x;
    int wid  = tid >> 5;
    int lane = tid & 31;
    int g = lane >> 2, t = lane & 3;
    int wm = (wid >> 2) * 64;
    int wn = (wid & 3) * 32;
    int m0 = blockIdx.y * 128;
    int n0 = blockIdx.x * 128;
    uint32_t sbase = smem_u32(hsm);

    float acc[4][4][4];
    #pragma unroll
    for (int i = 0; i < 4; i++)
        #pragma unroll
        for (int j = 0; j < 4; j++)
            #pragma unroll
            for (int e = 0; e < 4; e++) acc[i][j][e] = 0.f;

    auto load_stage = [&](int k0, int st) {
        #pragma unroll
        for (int p = 0; p < 2; p++) {
            int slot = tid + p * 256;                // 0..511
            int row  = slot >> 2;
            int col8 = (slot & 3) * 8;               // halves
            cp_async16(sbase + (uint32_t)((st * HTILE + row * HSTR + col8) * 2),
                       &g_xnh[(size_t)(m0 + row) * DD + k0 + col8]);
            cp_async16(sbase + (uint32_t)(((2 + st) * HTILE + row * HSTR + col8) * 2),
                       &W[(size_t)(n0 + row) * DD + k0 + col8]);
        }
        cp_commit();
    };

    load_stage(0, 0);
    for (int it = 0; it < DD / 32; it++) {
        int cur = it & 1;
        cp_wait0();
        __syncthreads();
        if (it < DD / 32 - 1) load_stage((it + 1) * 32, cur ^ 1);
        const __nv_bfloat16* As = hsm + cur * HTILE;
        const __nv_bfloat16* Bs = hsm + (2 + cur) * HTILE;
        #pragma unroll
        for (int ks = 0; ks < 2; ks++) {             // two k16 steps
            int kc = ks * 16 + 4 * t;                // perm16 frag base (halves)
            unsigned bf[4][2];
            #pragma unroll
            for (int n = 0; n < 4; n++) {
                uint2 bb = *(const uint2*)&Bs[(wn + n * 8 + g) * HSTR + kc];
                bf[n][0] = bb.x; bf[n][1] = bb.y;
            }
            #pragma unroll
            for (int mI = 0; mI < 4; mI++) {
                int rb = wm + mI * 16;
                uint2 aA = *(const uint2*)&As[(rb + g) * HSTR + kc];
                uint2 aB = *(const uint2*)&As[(rb + g + 8) * HSTR + kc];
                unsigned af[4] = {aA.x, aB.x, aA.y, aB.y};
                #pragma unroll
                for (int n = 0; n < 4; n++)
                    mma_bf16(acc[mI][n], af, bf[n], acc[mI][n]);
            }
        }
    }

    #pragma unroll
    for (int mI = 0; mI < 4; mI++) {
        int r0 = m0 + wm + mI * 16 + g;
        int bi0 = r0 >> 11, t0 = r0 & (TT - 1);
        #pragma unroll
        for (int n = 0; n < 4; n++) {
            int e = n0 + wn + n * 8 + 2 * t;         // natural pair (e, e+1)
            float bb0 = bias[e], bb1 = bias[e + 1];
            float v00 = acc[mI][n][0] + bb0, v01 = acc[mI][n][1] + bb1;
            float v10 = acc[mI][n][2] + bb0, v11 = acc[mI][n][3] + bb1;
            int h = e >> 6, dk = e & 63;
            int cl = dk & 15;                        // even
            int pos = (((cl >> 1) & 3) << 2) + (((cl >> 3) & 1) << 1);
            int dkp = (dk & ~15) + pos;              // pair -> dkp, dkp+1
            size_t base0 = (((size_t)(bi0 * HH + h) * TT + t0) << 6);
            size_t base1 = base0 + (8 << 6);
            *(__nv_bfloat162*)&C[base0 + dkp] = __floats2bfloat162_rn(v00, v01);
            *(__nv_bfloat162*)&C[base1 + dkp] = __floats2bfloat162_rn(v10, v11);
        }
    }
}

// ---------------- tf32 GEMM for V and O ----------------
#define GSTR 40
#define GTILE (128 * GSTR)
__global__ __launch_bounds__(256) void gemm_tc_kernel(
    const float* __restrict__ bias, int mode, float* __restrict__ dout) {
    extern __shared__ float gsm[];
    const float* W = g_wc + (size_t)(mode == 3 ? 1 : 0) * DD * DD;
    const float* Aptr = (mode == 2) ? g_xn : g_ao;

    int tid  = threadIdx.x;
    int wid  = tid >> 5;
    int lane = tid & 31;
    int g = lane >> 2, t = lane & 3;
    int wm = (wid >> 2) * 64;
    int wn = (wid & 3) * 32;
    int m0 = blockIdx.y * 128;
    int n0 = blockIdx.x * 128;
    uint32_t sbase = smem_u32(gsm);

    float acc[4][4][4];
    #pragma unroll
    for (int i = 0; i < 4; i++)
        #pragma unroll
        for (int j = 0; j < 4; j++)
            #pragma unroll
            for (int e = 0; e < 4; e++) acc[i][j][e] = 0.f;

    auto load_stage = [&](int k0, int st) {
        #pragma unroll
        for (int p = 0; p < 4; p++) {
            int slot = tid + p * 256;
            int row  = slot >> 3;
            int col4 = (slot & 7) * 4;
            cp_async16(sbase + (uint32_t)((st * GTILE + row * GSTR + col4) * 4),
                       &Aptr[(size_t)(m0 + row) * DD + k0 + col4]);
            cp_async16(sbase + (uint32_t)(((2 + st) * GTILE + row * GSTR + col4) * 4),
                       &W[(size_t)(n0 + row) * DD + k0 + col4]);
        }
        cp_commit();
    };

    load_stage(0, 0);
    for (int it = 0; it < DD / 32; it++) {
        int cur = it & 1;
        cp_wait0();
        __syncthreads();
        if (it < DD / 32 - 1) load_stage((it + 1) * 32, cur ^ 1);
        const float* As = gsm + cur * GTILE;
        const float* Bs = gsm + (2 + cur) * GTILE;
        #pragma unroll
        for (int ks = 0; ks < 4; ks++) {
            int kc = ks * 8 + 2 * t;
            unsigned bf[4][2];
            #pragma unroll
            for (int n = 0; n < 4; n++) {
                float2 bb = *(const float2*)&Bs[(wn + n * 8 + g) * GSTR + kc];
                bf[n][0] = __float_as_uint(bb.x);
                bf[n][1] = __float_as_uint(bb.y);
            }
            #pragma unroll
            for (int mI = 0; mI < 4; mI++) {
                int rb = wm + mI * 16;
                float2 aA = *(const float2*)&As[(rb + g) * GSTR + kc];
                float2 aB = *(const float2*)&As[(rb + g + 8) * GSTR + kc];
                unsigned af[4] = {__float_as_uint(aA.x), __float_as_uint(aB.x),
                                  __float_as_uint(aA.y), __float_as_uint(aB.y)};
                #pragma unroll
                for (int n = 0; n < 4; n++)
                    mma_tf32(acc[mI][n], af, bf[n], acc[mI][n]);
            }
        }
    }

    #pragma unroll
    for (int mI = 0; mI < 4; mI++) {
        int r0 = m0 + wm + mI * 16 + g;
        int bi0 = r0 >> 11, t0 = r0 & (TT - 1);
        #pragma unroll
        for (int n = 0; n < 4; n++) {
            int e = n0 + wn + n * 8 + 2 * t;
            float bb0 = bias[e], bb1 = bias[e + 1];
            float v00 = acc[mI][n][0] + bb0, v01 = acc[mI][n][1] + bb1;
            float v10 = acc[mI][n][2] + bb0, v11 = acc[mI][n][3] + bb1;
            if (mode == 3) {
                *(float2*)&dout[(size_t)r0 * DD + e] =
                    make_float2(v00 * 0.5f, v01 * 0.5f);
                *(float2*)&dout[(size_t)(r0 + 8) * DD + e] =
                    make_float2(v10 * 0.5f, v11 * 0.5f);
            } else {
                int h = e >> 6, dk = e & 63;
                // V block-transposed: [BH][T/64][DK][64key-perm8]
                int kt0 = t0 >> 6, ik = t0 & 63;
                int pk = (ik & ~7) | perm8(ik & 7);
                float* vb = g_v +
                    ((((size_t)(bi0 * HH + h) * (TT / 64) + kt0) * DKK + dk) << 6);
                vb[pk]          = f2tff(v00);
                vb[64 + pk]     = f2tff(v01);
                vb[pk + 8]      = f2tff(v10);
                vb[64 + pk + 8] = f2tff(v11);
            }
        }
    }
}

// ---------------- L2 normalize Q,K (bf16, order-invariant) ----------------
__global__ __launch_bounds__(256) void l2norm_kernel() {
    int warp = (blockIdx.x * blockDim.x + threadIdx.x) >> 5;
    int lane = threadIdx.x & 31;
    __nv_bfloat162* base =
        (__nv_bfloat162*)((blockIdx.y == 0) ? g_qh : g_kh);
    __nv_bfloat162* p = base + (size_t)warp * 32 + lane;
    float2 v = __bfloat1622float2(*p);
    float ss = v.x * v.x + v.y * v.y;
    #pragma unroll
    for (int o = 16; o > 0; o >>= 1) ss += __shfl_xor_sync(~0u, ss, o);
    float n = sqrtf(ss);
    float inv = 1.0f / fmaxf(n, EPS_NORM_);
    *p = __floats2bfloat162_rn(v.x * inv, v.y * inv);
}

// ---------------- Flash attention: bf16 S-stage, tf32 PV ----------------
// smem (bytes): K0,K1 bf16 64x80h (10240 each — FULL 64-half rows, 160B stride,
// conflict-free b64 frags: bank stride 40==8 mod 32); Vt0,Vt1 f32 64x72
// (18432 each); P f32 64x72 (18432, warp-private rows); mask 2048.
#define KH_STR 80
#define KH_TILE_B (64 * KH_STR * 2)          // 10240
#define VSTR 72
#define VT_TILE_B 18432
#define VT_OFF_B (2 * KH_TILE_B)
#define P_OFF_B (VT_OFF_B + 2 * VT_TILE_B)
#define MSK_OFF_B (P_OFF_B + VT_TILE_B)
#define ASMEM (MSK_OFF_B + TT)
__global__ __launch_bounds__(128) void attn_tc_kernel() {
    extern __shared__ char asmb[];
    unsigned char* Msk = (unsigned char*)(asmb + MSK_OFF_B);
    float* Ps = (float*)(asmb + P_OFF_B);

    int bh = blockIdx.y;
    int bi = bh >> 4;
    int h  = bh & 15;
    int qt = blockIdx.x;
    int tid = threadIdx.x;
    int wid = tid >> 5;
    int lane = tid & 31;
    int g = lane >> 2, t = lane & 3;
    int wg = wid * 16;
    uint32_t sbase = smem_u32(asmb);

    ((uint4*)Msk)[tid] = ((const uint4*)(g_cmask + bi * TT))[tid];

    // resident Q a-frags (bf16 perm16 -> b64 loads), 4 k16-steps
    unsigned qa[4][4];
    {
        const __nv_bfloat16* qp0 =
            g_qh + (((size_t)(bh * TT + qt * 64 + wg + g)) << 6);
        const __nv_bfloat16* qp1 = qp0 + (8 << 6);
        #pragma unroll
        for (int ks = 0; ks < 4; ks++) {
            uint2 xA = *(const uint2*)&qp0[ks * 16 + 4 * t];
            uint2 xB = *(const uint2*)&qp1[ks * 16 + 4 * t];
            qa[ks][0] = xA.x; qa[ks][1] = xB.x;
            qa[ks][2] = xA.y; qa[ks][3] = xB.y;
        }
    }

    float o_acc[8][4];
    #pragma unroll
    for (int n = 0; n < 8; n++)
        #pragma unroll
        for (int e = 0; e < 4; e++) o_acc[n][e] = 0.f;
    float psum0 = 0.f, psum1 = 0.f;

    const __nv_bfloat16* kbase = g_kh + (((size_t)bh * TT) << 6);
    const float* vbase = g_v + (((size_t)bh * TT) << 6);

    auto load_kv = [&](int kt, int st) {
        const __nv_bfloat16* kb = kbase + ((size_t)(kt * 64) << 6);
        const float* vb = vbase + ((size_t)(kt * 64) << 6);
        #pragma unroll
        for (int p = 0; p < 4; p++) {                // K: 512 16B-chunks
            int slot = tid + p * 128;
            int row  = slot >> 3;                    // 0..63
            int col8 = (slot & 7) * 8;               // 0..56 halves
            cp_async16(sbase + (uint32_t)(st * KH_TILE_B + (row * KH_STR + col8) * 2),
                       &kb[(row << 6) + col8]);
        }
        #pragma unroll
        for (int p = 0; p < 8; p++) {                // Vt: 1024 16B-chunks
            int slot = tid + p * 128;
            int row  = slot >> 4;
            int col4 = (slot & 15) * 4;
            cp_async16(sbase + (uint32_t)(VT_OFF_B + st * VT_TILE_B +
                                          (row * VSTR + col4) * 4),
                       &vb[(row << 6) + col4]);
        }
        cp_commit();
    };

    load_kv(0, 0);
    for (int kt = 0; kt < TT / 64; kt++) {
        int cur = kt & 1;
        cp_wait0();
        __syncthreads();
        if (kt < TT / 64 - 1) load_kv(kt + 1, cur ^ 1);

        const __nv_bfloat16* Ks = (const __nv_bfloat16*)(asmb + cur * KH_TILE_B);
        const float* Vs = (const float*)(asmb + VT_OFF_B + cur * VT_TILE_B);

        // S = Q.K^T  (bf16 m16n8k16; b-frags one b64 each)
        float sc[8][4];
        #pragma unroll
        for (int n = 0; n < 8; n++)
            #pragma unroll
            for (int e = 0; e < 4; e++) sc[n][e] = 0.f;
        #pragma unroll
        for (int ks = 0; ks < 4; ks++) {
            int kc = ks * 16 + 4 * t;
            #pragma unroll
            for (int n = 0; n < 8; n++) {
                uint2 kb2 = *(const uint2*)&Ks[(n * 8 + g) * KH_STR + kc];
                unsigned bf[2] = {kb2.x, kb2.y};
                mma_bf16(sc[n], qa[ks], bf, sc[n]);
            }
        }

        // static softmax weights; masked -> 0
        const unsigned char* mrow = Msk + kt * 64;
        #pragma unroll
        for (int n = 0; n < 8; n++) {
            bool mk0 = mrow[n * 8 + 2 * t] != 0;
            bool mk1 = mrow[n * 8 + 2 * t + 1] != 0;
            sc[n][0] = mk0 ? 0.f : __expf(sc[n][0] * SCALE_);
            sc[n][1] = mk1 ? 0.f : __expf(sc[n][1] * SCALE_);
            sc[n][2] = mk0 ? 0.f : __expf(sc[n][2] * SCALE_);
            sc[n][3] = mk1 ? 0.f : __expf(sc[n][3] * SCALE_);
            psum0 += sc[n][0] + sc[n][1];
            psum1 += sc[n][2] + sc[n][3];
        }

        // P (tf32) -> dedicated warp-private rows, key-perm8 columns
        #pragma unroll
        for (int n = 0; n < 8; n++) {
            int p0 = n * 8 + perm8(2 * t);
            Ps[(wg + g) * VSTR + p0]         = f2tff(sc[n][0]);
            Ps[(wg + g) * VSTR + p0 + 2]     = f2tff(sc[n][1]);
            Ps[(wg + g + 8) * VSTR + p0]     = f2tff(sc[n][2]);
            Ps[(wg + g + 8) * VSTR + p0 + 2] = f2tff(sc[n][3]);
        }
        __syncwarp();

        // O += P.V  (tf32, all-float2 feeds; Vt rows = dk, cols key-perm8)
        #pragma unroll
        for (int ks = 0; ks < 8; ks++) {
            int kc = ks * 8 + 2 * t;
            float2 pA = *(const float2*)&Ps[(wg + g) * VSTR + kc];
            float2 pB = *(const float2*)&Ps[(wg + g + 8) * VSTR + kc];
            unsigned pa[4] = {__float_as_uint(pA.x), __float_as_uint(pB.x),
                              __float_as_uint(pA.y), __float_as_uint(pB.y)};
            #pragma unroll
            for (int n = 0; n < 8; n++) {
                float2 vb2 = *(const float2*)&Vs[(n * 8 + g) * VSTR + kc];
                unsigned bf[2] = {__float_as_uint(vb2.x), __float_as_uint(vb2.y)};
                mma_tf32(o_acc[n], pa, bf, o_acc[n]);
            }
        }
        __syncwarp();
    }

    psum0 += __shfl_xor_sync(~0u, psum0, 1);
    psum0 += __shfl_xor_sync(~0u, psum0, 2);
    psum1 += __shfl_xor_sync(~0u, psum1, 1);
    psum1 += __shfl_xor_sync(~0u, psum1, 2);
    float inv0 = 1.0f / psum0;
    float inv1 = 1.0f / psum1;
    int tq0 = qt * 64 + wg + g;
    float* ob0 = g_ao + ((size_t)bi * TT + tq0) * DD + h * 64;
    float* ob1 = ob0 + 8 * DD;
    #pragma unroll
    for (int n = 0; n < 8; n++) {
        int p0 = n * 8 + perm8(2 * t);               // D-perm8 for O-GEMM feed
        ob0[p0]     = f2tff(o_acc[n][0] * inv0);
        ob0[p0 + 2] = f2tff(o_acc[n][1] * inv0);
        ob1[p0]     = f2tff(o_acc[n][2] * inv1);
        ob1[p0 + 2] = f2tff(o_acc[n][3] * inv1);
    }
}

// ---------------- launch ----------------
extern "C" void kernel_launch(void* const* d_in, const int* in_sizes, int n_in,
                              void* d_out, int out_size) {
    const float* x    = (const float*)d_in[0];
    const void*  mask = d_in[1];
    const float* wq = (const float*)d_in[2];
    const float* bq = (const float*)d_in[3];
    const float* wk = (const float*)d_in[4];
    const float* bk = (const float*)d_in[5];
    const float* wv = (const float*)d_in[6];
    const float* bv = (const float*)d_in[7];
    const float* wo = (const float*)d_in[8];
    const float* bo = (const float*)d_in[9];
    const float* ln_g = (const float*)d_in[10];
    const float* ln_b = (const float*)d_in[11];
    float* out = (float*)d_out;

    const int qk_smem   = 4 * HTILE * 2;             // 49152 B
    const int gemm_smem = 4 * GTILE * 4;             // 81920 B
    const int attn_smem = ASMEM;                     // 77824 B
    cudaFuncSetAttribute(gemm_qk_kernel,
        cudaFuncAttributeMaxDynamicSharedMemorySize, qk_smem);
    cudaFuncSetAttribute(gemm_tc_kernel,
        cudaFuncAttributeMaxDynamicSharedMemorySize, gemm_smem);
    cudaFuncSetAttribute(attn_tc_kernel,
        cudaFuncAttributeMaxDynamicSharedMemorySize, attn_smem);

    detect_mask_kernel<<<1, 256>>>((const unsigned char*)mask);
    convert_mask_kernel<<<(BB * TT + 255) / 256, 256>>>(mask);
    wconv_kernel<<<dim3(DD * DD / 1024, 4), 256>>>(wq, wk, wv, wo);
    ln_kernel<<<BB * TT, 256>>>(x, ln_g, ln_b);

    dim3 qk_grid(DD / 128, (BB * TT) / 128, 2);
    gemm_qk_kernel<<<qk_grid, 256, qk_smem>>>(bq, bk);

    dim3 vgrid(DD / 128, (BB * TT) / 128);
    gemm_tc_kernel<<<vgrid, 256, gemm_smem>>>(bv, 2, nullptr);

    dim3 l2grid((BB * HH * TT) / 8, 2);
    l2norm_kernel<<<l2grid, 256>>>();

    dim3 agrid(TT / 64, BB * HH);
    attn_tc_kernel<<<agrid, 128, attn_smem>>>();

    gemm_tc_kernel<<<vgrid, 256, gemm_smem>>>(bo, 3, out);
}

// round 11
// speedup vs baseline: 2.6821x; 1.4609x over previous
#include <cuda_runtime.h>
#include <cuda_bf16.h>
#include <cuda_fp16.h>
#include <cstdint>

#define BB 4
#define TT 2048
#define DD 1024
#define HH 16
#define DKK 64
#define SCALE_ 0.125f
#define EPS_LN_ 1e-5f
#define EPS_NORM_ 1e-8f

// within-16 perm: c -> 4*((c>>1)&3) + 2*((c>>3)&1) + (c&1)
// k16 frag halves {2t,2t+1,2t+8,2t+9} -> {4t..4t+3} (one b64)
__host__ __device__ __forceinline__ constexpr int perm16(int c) {
    return (((c >> 1) & 3) << 2) + (((c >> 3) & 1) << 1) + (c & 1);
}

// ---------------- scratch ----------------
__device__ __nv_bfloat16 g_xnh[BB * TT * DD];     // LN out bf16, D-perm16 (Q/K)
__device__ __half        g_xnf[BB * TT * DD];     // LN out fp16, D-perm16 (V)
__device__ __nv_bfloat16 g_qh[BB * HH * TT * DKK];// Q bf16, DK-perm16
__device__ __nv_bfloat16 g_kh[BB * HH * TT * DKK];// K bf16, DK-perm16
__device__ __half g_vh[BB * HH * TT * DKK];       // V fp16 [BH][T/64][DK][64 key-perm16]
__device__ __half g_aoh[BB * TT * DD];            // attn out fp16, D-perm16
__device__ __nv_bfloat16 g_wch[2 * DD * DD];      // wq, wk bf16 perm16
__device__ __half        g_wcf[2 * DD * DD];      // wv, wo fp16 perm16
__device__ unsigned char g_cmask[BB * TT];
__device__ int g_flags[3];

// ---------------- helpers ----------------
__device__ __forceinline__ void mma_bf16(float* d, const unsigned* a,
                                         const unsigned* b, const float* c) {
    asm volatile(
        "mma.sync.aligned.m16n8k16.row.col.f32.bf16.bf16.f32 "
        "{%0,%1,%2,%3}, {%4,%5,%6,%7}, {%8,%9}, {%10,%11,%12,%13};"
        : "=f"(d[0]), "=f"(d[1]), "=f"(d[2]), "=f"(d[3])
        : "r"(a[0]), "r"(a[1]), "r"(a[2]), "r"(a[3]),
          "r"(b[0]), "r"(b[1]),
          "f"(c[0]), "f"(c[1]), "f"(c[2]), "f"(c[3]));
}
__device__ __forceinline__ void mma_f16(float* d, const unsigned* a,
                                        const unsigned* b, const float* c) {
    asm volatile(
        "mma.sync.aligned.m16n8k16.row.col.f32.f16.f16.f32 "
        "{%0,%1,%2,%3}, {%4,%5,%6,%7}, {%8,%9}, {%10,%11,%12,%13};"
        : "=f"(d[0]), "=f"(d[1]), "=f"(d[2]), "=f"(d[3])
        : "r"(a[0]), "r"(a[1]), "r"(a[2]), "r"(a[3]),
          "r"(b[0]), "r"(b[1]),
          "f"(c[0]), "f"(c[1]), "f"(c[2]), "f"(c[3]));
}
__device__ __forceinline__ void cp_async16(uint32_t saddr, const void* gptr) {
    asm volatile("cp.async.cg.shared.global [%0], [%1], 16;\n" :: "r"(saddr), "l"(gptr));
}
__device__ __forceinline__ void cp_commit() { asm volatile("cp.async.commit_group;\n" ::); }
__device__ __forceinline__ void cp_wait0()  { asm volatile("cp.async.wait_group 0;\n" ::); }
__device__ __forceinline__ uint32_t smem_u32(const void* p) {
    return (uint32_t)__cvta_generic_to_shared(p);
}

// ---------------- mask detection / canonicalization ----------------
__global__ void detect_mask_kernel(const unsigned char* __restrict__ m) {
    if (threadIdx.x == 0) { g_flags[0] = 0; g_flags[1] = 0; g_flags[2] = 0; }
    __syncthreads();
    int a = 0, bhi = 0, c = 0;
    for (int i = threadIdx.x; i < BB * TT; i += blockDim.x) {
        unsigned char v = m[i];
        if (v) {
            int r = i & 3;
            if (r == 0) a = 1;
            else if (r == 1) c = 1;
            else bhi = 1;
        }
    }
    if (a)   atomicOr(&g_flags[0], 1);
    if (bhi) atomicOr(&g_flags[1], 1);
    if (c)   atomicOr(&g_flags[2], 1);
}
__global__ void convert_mask_kernel(const void* __restrict__ m) {
    int i = blockIdx.x * blockDim.x + threadIdx.x;
    if (i >= BB * TT) return;
    int A = g_flags[0], Bf = g_flags[1], C = g_flags[2];
    unsigned char out;
    if (A && !Bf && !C)      out = (((const int*)m)[i] != 0);
    else if (!A && Bf)       out = (((const float*)m)[i] != 0.0f);
    else                     out = (((const unsigned char*)m)[i] != 0);
    g_cmask[i] = out;
}

// ---------------- weight conversion: perm16, bf16 (q,k) / fp16 (v,o) -------
__global__ __launch_bounds__(256) void wconv_kernel(
    const float* __restrict__ w0, const float* __restrict__ w1,
    const float* __restrict__ w2, const float* __restrict__ w3) {
    int y = blockIdx.y;
    const float* src = (y == 0) ? w0 : (y == 1) ? w1 : (y == 2) ? w2 : w3;
    size_t i = ((size_t)blockIdx.x * 256 + threadIdx.x) * 4;
    float4 v = *(const float4*)&src[i];
    int r = (int)(i & 15);                           // 0,4,8,12
    int p0 = (((r >> 1) & 3) << 2) + (((r >> 3) & 1) << 1);
    size_t b16 = i & ~(size_t)15;
    if (y < 2) {
        __nv_bfloat16* dst = g_wch + (size_t)y * DD * DD;
        *(__nv_bfloat162*)&dst[b16 + p0]     = __floats2bfloat162_rn(v.x, v.y);
        *(__nv_bfloat162*)&dst[b16 + p0 + 4] = __floats2bfloat162_rn(v.z, v.w);
    } else {
        __half* dst = g_wcf + (size_t)(y - 2) * DD * DD;
        *(__half2*)&dst[b16 + p0]     = __floats2half2_rn(v.x, v.y);
        *(__half2*)&dst[b16 + p0 + 4] = __floats2half2_rn(v.z, v.w);
    }
}

// ---------------- LayerNorm: bf16 + fp16 perm16 outputs ----------------
__global__ __launch_bounds__(256) void ln_kernel(
    const float* __restrict__ x, const float* __restrict__ g,
    const float* __restrict__ b) {
    __shared__ float red_s[8], red_ss[8];
    int row = blockIdx.x;
    int tid = threadIdx.x;
    const float* xr = x + (size_t)row * DD;
    float4 xv = *(const float4*)&xr[tid * 4];
    float s  = xv.x + xv.y + xv.z + xv.w;
    float ss = xv.x*xv.x + xv.y*xv.y + xv.z*xv.z + xv.w*xv.w;
    #pragma unroll
    for (int o = 16; o > 0; o >>= 1) {
        s  += __shfl_xor_sync(~0u, s, o);
        ss += __shfl_xor_sync(~0u, ss, o);
    }
    int warp = tid >> 5, lane = tid & 31;
    if (lane == 0) { red_s[warp] = s; red_ss[warp] = ss; }
    __syncthreads();
    if (warp == 0) {
        s  = (lane < 8) ? red_s[lane]  : 0.f;
        ss = (lane < 8) ? red_ss[lane] : 0.f;
        #pragma unroll
        for (int o = 4; o > 0; o >>= 1) {
            s  += __shfl_xor_sync(~0u, s, o);
            ss += __shfl_xor_sync(~0u, ss, o);
        }
        if (lane == 0) { red_s[0] = s; red_ss[0] = ss; }
    }
    __syncthreads();
    float mu  = red_s[0] * (1.0f / DD);
    float var = red_ss[0] * (1.0f / DD) - mu * mu;
    float inv = rsqrtf(var + EPS_LN_);
    float4 gv = *(const float4*)&g[tid * 4];
    float4 bv = *(const float4*)&b[tid * 4];
    float y0 = (xv.x - mu) * inv * gv.x + bv.x;
    float y1 = (xv.y - mu) * inv * gv.y + bv.y;
    float y2 = (xv.z - mu) * inv * gv.z + bv.z;
    float y3 = (xv.w - mu) * inv * gv.w + bv.w;
    int c0 = tid * 4;
    int r = c0 & 15;
    int p0 = (((r >> 1) & 3) << 2) + (((r >> 3) & 1) << 1);
    size_t base = (size_t)row * DD + (c0 & ~15);
    __nv_bfloat16* hd = g_xnh + base;
    *(__nv_bfloat162*)&hd[p0]     = __floats2bfloat162_rn(y0, y1);
    *(__nv_bfloat162*)&hd[p0 + 4] = __floats2bfloat162_rn(y2, y3);
    __half* fd = g_xnf + base;
    *(__half2*)&fd[p0]     = __floats2half2_rn(y0, y1);
    *(__half2*)&fd[p0 + 4] = __floats2half2_rn(y2, y3);
}

// ---------------- bf16 GEMM for Q,K (R10, unchanged) ----------------
#define HSTR 48
#define HTILE (128 * HSTR)
__global__ __launch_bounds__(256) void gemm_qk_kernel(
    const float* __restrict__ bq, const float* __restrict__ bk) {
    extern __shared__ __nv_bfloat16 hsm[];
    int mode = blockIdx.z;
    const __nv_bfloat16* W = g_wch + (size_t)mode * DD * DD;
    const float* bias = mode ? bk : bq;
    __nv_bfloat16* C = mode ? g_kh : g_qh;

    int tid  = threadIdx.x;
    int wid  = tid >> 5;
    int lane = tid & 31;
    int g = lane >> 2, t = lane & 3;
    int wm = (wid >> 2) * 64;
    int wn = (wid & 3) * 32;
    int m0 = blockIdx.y * 128;
    int n0 = blockIdx.x * 128;
    uint32_t sbase = smem_u32(hsm);

    float acc[4][4][4];
    #pragma unroll
    for (int i = 0; i < 4; i++)
        #pragma unroll
        for (int j = 0; j < 4; j++)
            #pragma unroll
            for (int e = 0; e < 4; e++) acc[i][j][e] = 0.f;

    auto load_stage = [&](int k0, int st) {
        #pragma unroll
        for (int p = 0; p < 2; p++) {
            int slot = tid + p * 256;
            int row  = slot >> 2;
            int col8 = (slot & 3) * 8;
            cp_async16(sbase + (uint32_t)((st * HTILE + row * HSTR + col8) * 2),
                       &g_xnh[(size_t)(m0 + row) * DD + k0 + col8]);
            cp_async16(sbase + (uint32_t)(((2 + st) * HTILE + row * HSTR + col8) * 2),
                       &W[(size_t)(n0 + row) * DD + k0 + col8]);
        }
        cp_commit();
    };

    load_stage(0, 0);
    for (int it = 0; it < DD / 32; it++) {
        int cur = it & 1;
        cp_wait0();
        __syncthreads();
        if (it < DD / 32 - 1) load_stage((it + 1) * 32, cur ^ 1);
        const __nv_bfloat16* As = hsm + cur * HTILE;
        const __nv_bfloat16* Bs = hsm + (2 + cur) * HTILE;
        #pragma unroll
        for (int ks = 0; ks < 2; ks++) {
            int kc = ks * 16 + 4 * t;
            unsigned bf[4][2];
            #pragma unroll
            for (int n = 0; n < 4; n++) {
                uint2 bb = *(const uint2*)&Bs[(wn + n * 8 + g) * HSTR + kc];
                bf[n][0] = bb.x; bf[n][1] = bb.y;
            }
            #pragma unroll
            for (int mI = 0; mI < 4; mI++) {
                int rb = wm + mI * 16;
                uint2 aA = *(const uint2*)&As[(rb + g) * HSTR + kc];
                uint2 aB = *(const uint2*)&As[(rb + g + 8) * HSTR + kc];
                unsigned af[4] = {aA.x, aB.x, aA.y, aB.y};
                #pragma unroll
                for (int n = 0; n < 4; n++)
                    mma_bf16(acc[mI][n], af, bf[n], acc[mI][n]);
            }
        }
    }

    #pragma unroll
    for (int mI = 0; mI < 4; mI++) {
        int r0 = m0 + wm + mI * 16 + g;
        int bi0 = r0 >> 11, t0 = r0 & (TT - 1);
        #pragma unroll
        for (int n = 0; n < 4; n++) {
            int e = n0 + wn + n * 8 + 2 * t;
            float bb0 = bias[e], bb1 = bias[e + 1];
            float v00 = acc[mI][n][0] + bb0, v01 = acc[mI][n][1] + bb1;
            float v10 = acc[mI][n][2] + bb0, v11 = acc[mI][n][3] + bb1;
            int h = e >> 6, dk = e & 63;
            int cl = dk & 15;
            int pos = (((cl >> 1) & 3) << 2) + (((cl >> 3) & 1) << 1);
            int dkp = (dk & ~15) + pos;
            size_t base0 = (((size_t)(bi0 * HH + h) * TT + t0) << 6);
            size_t base1 = base0 + (8 << 6);
            *(__nv_bfloat162*)&C[base0 + dkp] = __floats2bfloat162_rn(v00, v01);
            *(__nv_bfloat162*)&C[base1 + dkp] = __floats2bfloat162_rn(v10, v11);
        }
    }
}

// ---------------- fp16 GEMM for V (mode 2) and O (mode 3) ----------------
__global__ __launch_bounds__(256) void gemm_vo_kernel(
    const float* __restrict__ bias, int mode, float* __restrict__ dout) {
    extern __shared__ __half fsm[];
    const __half* W = g_wcf + (size_t)(mode == 3 ? 1 : 0) * DD * DD;
    const __half* Aptr = (mode == 2) ? g_xnf : g_aoh;

    int tid  = threadIdx.x;
    int wid  = tid >> 5;
    int lane = tid & 31;
    int g = lane >> 2, t = lane & 3;
    int wm = (wid >> 2) * 64;
    int wn = (wid & 3) * 32;
    int m0 = blockIdx.y * 128;
    int n0 = blockIdx.x * 128;
    uint32_t sbase = smem_u32(fsm);

    float acc[4][4][4];
    #pragma unroll
    for (int i = 0; i < 4; i++)
        #pragma unroll
        for (int j = 0; j < 4; j++)
            #pragma unroll
            for (int e = 0; e < 4; e++) acc[i][j][e] = 0.f;

    auto load_stage = [&](int k0, int st) {
        #pragma unroll
        for (int p = 0; p < 2; p++) {
            int slot = tid + p * 256;
            int row  = slot >> 2;
            int col8 = (slot & 3) * 8;
            cp_async16(sbase + (uint32_t)((st * HTILE + row * HSTR + col8) * 2),
                       &Aptr[(size_t)(m0 + row) * DD + k0 + col8]);
            cp_async16(sbase + (uint32_t)(((2 + st) * HTILE + row * HSTR + col8) * 2),
                       &W[(size_t)(n0 + row) * DD + k0 + col8]);
        }
        cp_commit();
    };

    load_stage(0, 0);
    for (int it = 0; it < DD / 32; it++) {
        int cur = it & 1;
        cp_wait0();
        __syncthreads();
        if (it < DD / 32 - 1) load_stage((it + 1) * 32, cur ^ 1);
        const __half* As = fsm + cur * HTILE;
        const __half* Bs = fsm + (2 + cur) * HTILE;
        #pragma unroll
        for (int ks = 0; ks < 2; ks++) {
            int kc = ks * 16 + 4 * t;
            unsigned bf[4][2];
            #pragma unroll
            for (int n = 0; n < 4; n++) {
                uint2 bb = *(const uint2*)&Bs[(wn + n * 8 + g) * HSTR + kc];
                bf[n][0] = bb.x; bf[n][1] = bb.y;
            }
            #pragma unroll
            for (int mI = 0; mI < 4; mI++) {
                int rb = wm + mI * 16;
                uint2 aA = *(const uint2*)&As[(rb + g) * HSTR + kc];
                uint2 aB = *(const uint2*)&As[(rb + g + 8) * HSTR + kc];
                unsigned af[4] = {aA.x, aB.x, aA.y, aB.y};
                #pragma unroll
                for (int n = 0; n < 4; n++)
                    mma_f16(acc[mI][n], af, bf[n], acc[mI][n]);
            }
        }
    }

    #pragma unroll
    for (int mI = 0; mI < 4; mI++) {
        int r0 = m0 + wm + mI * 16 + g;
        int bi0 = r0 >> 11, t0 = r0 & (TT - 1);
        #pragma unroll
        for (int n = 0; n < 4; n++) {
            int e = n0 + wn + n * 8 + 2 * t;
            float bb0 = bias[e], bb1 = bias[e + 1];
            float v00 = acc[mI][n][0] + bb0, v01 = acc[mI][n][1] + bb1;
            float v10 = acc[mI][n][2] + bb0, v11 = acc[mI][n][3] + bb1;
            if (mode == 3) {
                *(float2*)&dout[(size_t)r0 * DD + e] =
                    make_float2(v00 * 0.5f, v01 * 0.5f);
                *(float2*)&dout[(size_t)(r0 + 8) * DD + e] =
                    make_float2(v10 * 0.5f, v11 * 0.5f);
            } else {
                int h = e >> 6, dk = e & 63;
                // V fp16 block-transposed: [BH][T/64][DK][64 key-perm16]
                int kt0 = t0 >> 6, ik = t0 & 63;     // ik&15 == g (wm,mI*16 mult of 16)
                int pk = (ik & ~15) | perm16(ik & 15);
                // key t0+8: class (ik&15)+8 -> perm16 +2
                __half* vb = g_vh +
                    ((((size_t)(bi0 * HH + h) * (TT / 64) + kt0) * DKK + dk) << 6);
                vb[pk]          = __float2half_rn(v00);
                vb[64 + pk]     = __float2half_rn(v01);   // dk+1
                vb[pk + 2]      = __float2half_rn(v10);   // key t0+8
                vb[64 + pk + 2] = __float2half_rn(v11);
            }
        }
    }
}

// ---------------- L2 normalize Q,K (bf16, order-invariant) ----------------
__global__ __launch_bounds__(256) void l2norm_kernel() {
    int warp = (blockIdx.x * blockDim.x + threadIdx.x) >> 5;
    int lane = threadIdx.x & 31;
    __nv_bfloat162* base =
        (__nv_bfloat162*)((blockIdx.y == 0) ? g_qh : g_kh);
    __nv_bfloat162* p = base + (size_t)warp * 32 + lane;
    float2 v = __bfloat1622float2(*p);
    float ss = v.x * v.x + v.y * v.y;
    #pragma unroll
    for (int o = 16; o > 0; o >>= 1) ss += __shfl_xor_sync(~0u, ss, o);
    float n = sqrtf(ss);
    float inv = 1.0f / fmaxf(n, EPS_NORM_);
    *p = __floats2bfloat162_rn(v.x * inv, v.y * inv);
}

// ---------------- Flash attention: bf16 S, fp16 PV ----------------
// smem: K0,K1 bf16 64x80h (10240 B each); Vt0,Vt1 fp16 64x80h (10240 each);
// P fp16 64x80h (10240, warp-private rows); mask 2048.  Total 53248 B.
#define KH_STR 80
#define KH_TILE_B (64 * KH_STR * 2)
#define VH_STR 80
#define VH_TILE_B (64 * VH_STR * 2)
#define VT_OFF_B (2 * KH_TILE_B)
#define P_OFF_B (VT_OFF_B + 2 * VH_TILE_B)
#define MSK_OFF_B (P_OFF_B + VH_TILE_B)
#define ASMEM (MSK_OFF_B + TT)
__global__ __launch_bounds__(128) void attn_tc_kernel() {
    extern __shared__ char asmb[];
    unsigned char* Msk = (unsigned char*)(asmb + MSK_OFF_B);
    __half* Ps = (__half*)(asmb + P_OFF_B);

    int bh = blockIdx.y;
    int bi = bh >> 4;
    int h  = bh & 15;
    int qt = blockIdx.x;
    int tid = threadIdx.x;
    int wid = tid >> 5;
    int lane = tid & 31;
    int g = lane >> 2, t = lane & 3;
    int wg = wid * 16;
    uint32_t sbase = smem_u32(asmb);

    ((uint4*)Msk)[tid] = ((const uint4*)(g_cmask + bi * TT))[tid];

    // resident Q a-frags (bf16 perm16 -> b64 loads)
    unsigned qa[4][4];
    {
        const __nv_bfloat16* qp0 =
            g_qh + (((size_t)(bh * TT + qt * 64 + wg + g)) << 6);
        const __nv_bfloat16* qp1 = qp0 + (8 << 6);
        #pragma unroll
        for (int ks = 0; ks < 4; ks++) {
            uint2 xA = *(const uint2*)&qp0[ks * 16 + 4 * t];
            uint2 xB = *(const uint2*)&qp1[ks * 16 + 4 * t];
            qa[ks][0] = xA.x; qa[ks][1] = xB.x;
            qa[ks][2] = xA.y; qa[ks][3] = xB.y;
        }
    }

    float o_acc[8][4];
    #pragma unroll
    for (int n = 0; n < 8; n++)
        #pragma unroll
        for (int e = 0; e < 4; e++) o_acc[n][e] = 0.f;
    float psum0 = 0.f, psum1 = 0.f;

    const __nv_bfloat16* kbase = g_kh + (((size_t)bh * TT) << 6);
    const __half* vbase = g_vh + (((size_t)bh * TT) << 6);   // tile kt at kt*4096

    auto load_kv = [&](int kt, int st) {
        const __nv_bfloat16* kb = kbase + ((size_t)(kt * 64) << 6);
        const __half* vb = vbase + ((size_t)kt << 12);        // [dk][64 key-perm16]
        #pragma unroll
        for (int p = 0; p < 4; p++) {                 // K: 512 16B chunks
            int slot = tid + p * 128;
            int row  = slot >> 3;
            int col8 = (slot & 7) * 8;
            cp_async16(sbase + (uint32_t)(st * KH_TILE_B + (row * KH_STR + col8) * 2),
                       &kb[(row << 6) + col8]);
        }
        #pragma unroll
        for (int p = 0; p < 4; p++) {                 // Vt: 512 16B chunks
            int slot = tid + p * 128;
            int row  = slot >> 3;
            int col8 = (slot & 7) * 8;
            cp_async16(sbase + (uint32_t)(VT_OFF_B + st * VH_TILE_B +
                                          (row * VH_STR + col8) * 2),
                       &vb[(row << 6) + col8]);
        }
        cp_commit();
    };

    load_kv(0, 0);
    for (int kt = 0; kt < TT / 64; kt++) {
        int cur = kt & 1;
        cp_wait0();
        __syncthreads();
        if (kt < TT / 64 - 1) load_kv(kt + 1, cur ^ 1);

        const __nv_bfloat16* Ks = (const __nv_bfloat16*)(asmb + cur * KH_TILE_B);
        const __half* Vs = (const __half*)(asmb + VT_OFF_B + cur * VH_TILE_B);

        // S = Q.K^T (bf16)
        float sc[8][4];
        #pragma unroll
        for (int n = 0; n < 8; n++)
            #pragma unroll
            for (int e = 0; e < 4; e++) sc[n][e] = 0.f;
        #pragma unroll
        for (int ks = 0; ks < 4; ks++) {
            int kc = ks * 16 + 4 * t;
            #pragma unroll
            for (int n = 0; n < 8; n++) {
                uint2 kb2 = *(const uint2*)&Ks[(n * 8 + g) * KH_STR + kc];
                unsigned bf[2] = {kb2.x, kb2.y};
                mma_bf16(sc[n], qa[ks], bf, sc[n]);
            }
        }

        // static softmax; masked -> 0
        const unsigned char* mrow = Msk + kt * 64;
        #pragma unroll
        for (int n = 0; n < 8; n++) {
            bool mk0 = mrow[n * 8 + 2 * t] != 0;
            bool mk1 = mrow[n * 8 + 2 * t + 1] != 0;
            sc[n][0] = mk0 ? 0.f : __expf(sc[n][0] * SCALE_);
            sc[n][1] = mk1 ? 0.f : __expf(sc[n][1] * SCALE_);
            sc[n][2] = mk0 ? 0.f : __expf(sc[n][2] * SCALE_);
            sc[n][3] = mk1 ? 0.f : __expf(sc[n][3] * SCALE_);
            psum0 += sc[n][0] + sc[n][1];
            psum1 += sc[n][2] + sc[n][3];
        }

        // P fp16 -> warp-private rows, key-perm16 columns (half2 stores)
        #pragma unroll
        for (int n = 0; n < 8; n++) {
            int pc = (n >> 1) * 16 + 4 * t + 2 * (n & 1);
            *(__half2*)&Ps[(wg + g) * VH_STR + pc] =
                __floats2half2_rn(sc[n][0], sc[n][1]);
            *(__half2*)&Ps[(wg + g + 8) * VH_STR + pc] =
                __floats2half2_rn(sc[n][2], sc[n][3]);
        }
        __syncwarp();

        // O += P.V (fp16 m16n8k16)
        #pragma unroll
        for (int ks = 0; ks < 4; ks++) {
            int kc = ks * 16 + 4 * t;
            uint2 pA = *(const uint2*)&Ps[(wg + g) * VH_STR + kc];
            uint2 pB = *(const uint2*)&Ps[(wg + g + 8) * VH_STR + kc];
            unsigned pa[4] = {pA.x, pB.x, pA.y, pB.y};
            #pragma unroll
            for (int n = 0; n < 8; n++) {
                uint2 vb2 = *(const uint2*)&Vs[(n * 8 + g) * VH_STR + kc];
                unsigned bf[2] = {vb2.x, vb2.y};
                mma_f16(o_acc[n], pa, bf, o_acc[n]);
            }
        }
        __syncwarp();
    }

    psum0 += __shfl_xor_sync(~0u, psum0, 1);
    psum0 += __shfl_xor_sync(~0u, psum0, 2);
    psum1 += __shfl_xor_sync(~0u, psum1, 1);
    psum1 += __shfl_xor_sync(~0u, psum1, 2);
    float inv0 = 1.0f / psum0;
    float inv1 = 1.0f / psum1;
    int tq0 = qt * 64 + wg + g;
    __half* ob0 = g_aoh + ((size_t)bi * TT + tq0) * DD + h * 64;
    __half* ob1 = ob0 + 8 * DD;
    #pragma unroll
    for (int n = 0; n < 8; n++) {
        int pc = (n >> 1) * 16 + 4 * t + 2 * (n & 1);   // D-perm16
        *(__half2*)&ob0[pc] =
            __floats2half2_rn(o_acc[n][0] * inv0, o_acc[n][1] * inv0);
        *(__half2*)&ob1[pc] =
            __floats2half2_rn(o_acc[n][2] * inv1, o_acc[n][3] * inv1);
    }
}

// ---------------- launch ----------------
extern "C" void kernel_launch(void* const* d_in, const int* in_sizes, int n_in,
                              void* d_out, int out_size) {
    const float* x    = (const float*)d_in[0];
    const void*  mask = d_in[1];
    const float* wq = (const float*)d_in[2];
    const float* bq = (const float*)d_in[3];
    const float* wk = (const float*)d_in[4];
    const float* bk = (const float*)d_in[5];
    const float* wv = (const float*)d_in[6];
    const float* bv = (const float*)d_in[7];
    const float* wo = (const float*)d_in[8];
    const float* bo = (const float*)d_in[9];
    const float* ln_g = (const float*)d_in[10];
    const float* ln_b = (const float*)d_in[11];
    float* out = (float*)d_out;

    const int h_smem    = 4 * HTILE * 2;             // 49152 B
    const int attn_smem = ASMEM;                     // 53248 B
    cudaFuncSetAttribute(gemm_qk_kernel,
        cudaFuncAttributeMaxDynamicSharedMemorySize, h_smem);
    cudaFuncSetAttribute(gemm_vo_kernel,
        cudaFuncAttributeMaxDynamicSharedMemorySize, h_smem);
    cudaFuncSetAttribute(attn_tc_kernel,
        cudaFuncAttributeMaxDynamicSharedMemorySize, attn_smem);

    detect_mask_kernel<<<1, 256>>>((const unsigned char*)mask);
    convert_mask_kernel<<<(BB * TT + 255) / 256, 256>>>(mask);
    wconv_kernel<<<dim3(DD * DD / 1024, 4), 256>>>(wq, wk, wv, wo);
    ln_kernel<<<BB * TT, 256>>>(x, ln_g, ln_b);

    dim3 qk_grid(DD / 128, (BB * TT) / 128, 2);
    gemm_qk_kernel<<<qk_grid, 256, h_smem>>>(bq, bk);

    dim3 vgrid(DD / 128, (BB * TT) / 128);
    gemm_vo_kernel<<<vgrid, 256, h_smem>>>(bv, 2, nullptr);

    dim3 l2grid((BB * HH * TT) / 8, 2);
    l2norm_kernel<<<l2grid, 256>>>();

    dim3 agrid(TT / 64, BB * HH);
    attn_tc_kernel<<<agrid, 128, attn_smem>>>();

    gemm_vo_kernel<<<vgrid, 256, h_smem>>>(bo, 3, out);
}

// round 12
// speedup vs baseline: 2.7257x; 1.0163x over previous
#include <cuda_runtime.h>
#include <cuda_bf16.h>
#include <cuda_fp16.h>
#include <cstdint>

#define BB 4
#define TT 2048
#define DD 1024
#define HH 16
#define DKK 64
#define SCALE_ 0.125f
#define SC2_ 0.18033688011112042f   // 0.125 * log2(e)
#define EPS_LN_ 1e-5f
#define EPS_NORM_ 1e-8f

// within-16 perm: c -> 4*((c>>1)&3) + 2*((c>>3)&1) + (c&1)
__host__ __device__ __forceinline__ constexpr int perm16(int c) {
    return (((c >> 1) & 3) << 2) + (((c >> 3) & 1) << 1) + (c & 1);
}

// ---------------- scratch ----------------
__device__ __nv_bfloat16 g_xnh[BB * TT * DD];     // LN out bf16, D-perm16 (Q/K)
__device__ __half        g_xnf[BB * TT * DD];     // LN out fp16, D-perm16 (V)
__device__ __nv_bfloat16 g_qh[BB * HH * TT * DKK];// Q bf16, DK-perm16
__device__ __nv_bfloat16 g_kh[BB * HH * TT * DKK];// K bf16, DK-perm16
__device__ __half g_vh[BB * HH * TT * DKK];       // V fp16 [BH][T/64][DK][64 key-perm16]
__device__ __half g_aoh[BB * TT * DD];            // attn out fp16, D-perm16
__device__ __nv_bfloat16 g_wch[2 * DD * DD];      // wq, wk bf16 perm16
__device__ __half        g_wcf[2 * DD * DD];      // wv, wo fp16 perm16
__device__ unsigned char g_cmask[BB * TT];
__device__ int g_flags[3];

// ---------------- helpers ----------------
__device__ __forceinline__ void mma_bf16(float* d, const unsigned* a,
                                         const unsigned* b, const float* c) {
    asm volatile(
        "mma.sync.aligned.m16n8k16.row.col.f32.bf16.bf16.f32 "
        "{%0,%1,%2,%3}, {%4,%5,%6,%7}, {%8,%9}, {%10,%11,%12,%13};"
        : "=f"(d[0]), "=f"(d[1]), "=f"(d[2]), "=f"(d[3])
        : "r"(a[0]), "r"(a[1]), "r"(a[2]), "r"(a[3]),
          "r"(b[0]), "r"(b[1]),
          "f"(c[0]), "f"(c[1]), "f"(c[2]), "f"(c[3]));
}
__device__ __forceinline__ void mma_f16(float* d, const unsigned* a,
                                        const unsigned* b, const float* c) {
    asm volatile(
        "mma.sync.aligned.m16n8k16.row.col.f32.f16.f16.f32 "
        "{%0,%1,%2,%3}, {%4,%5,%6,%7}, {%8,%9}, {%10,%11,%12,%13};"
        : "=f"(d[0]), "=f"(d[1]), "=f"(d[2]), "=f"(d[3])
        : "r"(a[0]), "r"(a[1]), "r"(a[2]), "r"(a[3]),
          "r"(b[0]), "r"(b[1]),
          "f"(c[0]), "f"(c[1]), "f"(c[2]), "f"(c[3]));
}
__device__ __forceinline__ void cp_async16(uint32_t saddr, const void* gptr) {
    asm volatile("cp.async.cg.shared.global [%0], [%1], 16;\n" :: "r"(saddr), "l"(gptr));
}
__device__ __forceinline__ void cp_commit() { asm volatile("cp.async.commit_group;\n" ::); }
__device__ __forceinline__ void cp_wait0()  { asm volatile("cp.async.wait_group 0;\n" ::); }
__device__ __forceinline__ void cp_wait1()  { asm volatile("cp.async.wait_group 1;\n" ::); }
__device__ __forceinline__ uint32_t smem_u32(const void* p) {
    return (uint32_t)__cvta_generic_to_shared(p);
}
__device__ __forceinline__ float fexp2(float x) {
    float r;
    asm("ex2.approx.f32 %0, %1;" : "=f"(r) : "f"(x));
    return r;
}

// ---------------- mask detection / canonicalization ----------------
__global__ void detect_mask_kernel(const unsigned char* __restrict__ m) {
    if (threadIdx.x == 0) { g_flags[0] = 0; g_flags[1] = 0; g_flags[2] = 0; }
    __syncthreads();
    int a = 0, bhi = 0, c = 0;
    for (int i = threadIdx.x; i < BB * TT; i += blockDim.x) {
        unsigned char v = m[i];
        if (v) {
            int r = i & 3;
            if (r == 0) a = 1;
            else if (r == 1) c = 1;
            else bhi = 1;
        }
    }
    if (a)   atomicOr(&g_flags[0], 1);
    if (bhi) atomicOr(&g_flags[1], 1);
    if (c)   atomicOr(&g_flags[2], 1);
}
__global__ void convert_mask_kernel(const void* __restrict__ m) {
    int i = blockIdx.x * blockDim.x + threadIdx.x;
    if (i >= BB * TT) return;
    int A = g_flags[0], Bf = g_flags[1], C = g_flags[2];
    unsigned char out;
    if (A && !Bf && !C)      out = (((const int*)m)[i] != 0);
    else if (!A && Bf)       out = (((const float*)m)[i] != 0.0f);
    else                     out = (((const unsigned char*)m)[i] != 0);
    g_cmask[i] = out;
}

// ---------------- weight conversion: perm16, bf16 (q,k) / fp16 (v,o) -------
__global__ __launch_bounds__(256) void wconv_kernel(
    const float* __restrict__ w0, const float* __restrict__ w1,
    const float* __restrict__ w2, const float* __restrict__ w3) {
    int y = blockIdx.y;
    const float* src = (y == 0) ? w0 : (y == 1) ? w1 : (y == 2) ? w2 : w3;
    size_t i = ((size_t)blockIdx.x * 256 + threadIdx.x) * 4;
    float4 v = *(const float4*)&src[i];
    int r = (int)(i & 15);
    int p0 = (((r >> 1) & 3) << 2) + (((r >> 3) & 1) << 1);
    size_t b16 = i & ~(size_t)15;
    if (y < 2) {
        __nv_bfloat16* dst = g_wch + (size_t)y * DD * DD;
        *(__nv_bfloat162*)&dst[b16 + p0]     = __floats2bfloat162_rn(v.x, v.y);
        *(__nv_bfloat162*)&dst[b16 + p0 + 4] = __floats2bfloat162_rn(v.z, v.w);
    } else {
        __half* dst = g_wcf + (size_t)(y - 2) * DD * DD;
        *(__half2*)&dst[b16 + p0]     = __floats2half2_rn(v.x, v.y);
        *(__half2*)&dst[b16 + p0 + 4] = __floats2half2_rn(v.z, v.w);
    }
}

// ---------------- LayerNorm: bf16 + fp16 perm16 outputs ----------------
__global__ __launch_bounds__(256) void ln_kernel(
    const float* __restrict__ x, const float* __restrict__ g,
    const float* __restrict__ b) {
    __shared__ float red_s[8], red_ss[8];
    int row = blockIdx.x;
    int tid = threadIdx.x;
    const float* xr = x + (size_t)row * DD;
    float4 xv = *(const float4*)&xr[tid * 4];
    float s  = xv.x + xv.y + xv.z + xv.w;
    float ss = xv.x*xv.x + xv.y*xv.y + xv.z*xv.z + xv.w*xv.w;
    #pragma unroll
    for (int o = 16; o > 0; o >>= 1) {
        s  += __shfl_xor_sync(~0u, s, o);
        ss += __shfl_xor_sync(~0u, ss, o);
    }
    int warp = tid >> 5, lane = tid & 31;
    if (lane == 0) { red_s[warp] = s; red_ss[warp] = ss; }
    __syncthreads();
    if (warp == 0) {
        s  = (lane < 8) ? red_s[lane]  : 0.f;
        ss = (lane < 8) ? red_ss[lane] : 0.f;
        #pragma unroll
        for (int o = 4; o > 0; o >>= 1) {
            s  += __shfl_xor_sync(~0u, s, o);
            ss += __shfl_xor_sync(~0u, ss, o);
        }
        if (lane == 0) { red_s[0] = s; red_ss[0] = ss; }
    }
    __syncthreads();
    float mu  = red_s[0] * (1.0f / DD);
    float var = red_ss[0] * (1.0f / DD) - mu * mu;
    float inv = rsqrtf(var + EPS_LN_);
    float4 gv = *(const float4*)&g[tid * 4];
    float4 bv = *(const float4*)&b[tid * 4];
    float y0 = (xv.x - mu) * inv * gv.x + bv.x;
    float y1 = (xv.y - mu) * inv * gv.y + bv.y;
    float y2 = (xv.z - mu) * inv * gv.z + bv.z;
    float y3 = (xv.w - mu) * inv * gv.w + bv.w;
    int c0 = tid * 4;
    int r = c0 & 15;
    int p0 = (((r >> 1) & 3) << 2) + (((r >> 3) & 1) << 1);
    size_t base = (size_t)row * DD + (c0 & ~15);
    __nv_bfloat16* hd = g_xnh + base;
    *(__nv_bfloat162*)&hd[p0]     = __floats2bfloat162_rn(y0, y1);
    *(__nv_bfloat162*)&hd[p0 + 4] = __floats2bfloat162_rn(y2, y3);
    __half* fd = g_xnf + base;
    *(__half2*)&fd[p0]     = __floats2half2_rn(y0, y1);
    *(__half2*)&fd[p0 + 4] = __floats2half2_rn(y2, y3);
}

// ---------------- bf16 GEMM for Q,K: 3-stage cp.async ----------------
#define HSTR 48
#define HTILE (128 * HSTR)
#define NIT (DD / 32)
__global__ __launch_bounds__(256) void gemm_qk_kernel(
    const float* __restrict__ bq, const float* __restrict__ bk) {
    extern __shared__ __nv_bfloat16 hsm[];
    int mode = blockIdx.z;
    const __nv_bfloat16* W = g_wch + (size_t)mode * DD * DD;
    const float* bias = mode ? bk : bq;
    __nv_bfloat16* C = mode ? g_kh : g_qh;

    int tid  = threadIdx.x;
    int wid  = tid >> 5;
    int lane = tid & 31;
    int g = lane >> 2, t = lane & 3;
    int wm = (wid >> 2) * 64;
    int wn = (wid & 3) * 32;
    int m0 = blockIdx.y * 128;
    int n0 = blockIdx.x * 128;
    uint32_t sbase = smem_u32(hsm);

    float acc[4][4][4];
    #pragma unroll
    for (int i = 0; i < 4; i++)
        #pragma unroll
        for (int j = 0; j < 4; j++)
            #pragma unroll
            for (int e = 0; e < 4; e++) acc[i][j][e] = 0.f;

    auto load_stage = [&](int k0, int st) {
        #pragma unroll
        for (int p = 0; p < 2; p++) {
            int slot = tid + p * 256;
            int row  = slot >> 2;
            int col8 = (slot & 3) * 8;
            cp_async16(sbase + (uint32_t)((st * HTILE + row * HSTR + col8) * 2),
                       &g_xnh[(size_t)(m0 + row) * DD + k0 + col8]);
            cp_async16(sbase + (uint32_t)(((3 + st) * HTILE + row * HSTR + col8) * 2),
                       &W[(size_t)(n0 + row) * DD + k0 + col8]);
        }
        cp_commit();
    };

    load_stage(0, 0);
    load_stage(32, 1);
    for (int it = 0; it < NIT; it++) {
        int cur = it % 3;
        if (it + 1 < NIT) cp_wait1(); else cp_wait0();
        __syncthreads();
        if (it + 2 < NIT) load_stage((it + 2) * 32, (it + 2) % 3);
        const __nv_bfloat16* As = hsm + cur * HTILE;
        const __nv_bfloat16* Bs = hsm + (3 + cur) * HTILE;
        #pragma unroll
        for (int ks = 0; ks < 2; ks++) {
            int kc = ks * 16 + 4 * t;
            unsigned bf[4][2];
            #pragma unroll
            for (int n = 0; n < 4; n++) {
                uint2 bb = *(const uint2*)&Bs[(wn + n * 8 + g) * HSTR + kc];
                bf[n][0] = bb.x; bf[n][1] = bb.y;
            }
            #pragma unroll
            for (int mI = 0; mI < 4; mI++) {
                int rb = wm + mI * 16;
                uint2 aA = *(const uint2*)&As[(rb + g) * HSTR + kc];
                uint2 aB = *(const uint2*)&As[(rb + g + 8) * HSTR + kc];
                unsigned af[4] = {aA.x, aB.x, aA.y, aB.y};
                #pragma unroll
                for (int n = 0; n < 4; n++)
                    mma_bf16(acc[mI][n], af, bf[n], acc[mI][n]);
            }
        }
    }

    #pragma unroll
    for (int mI = 0; mI < 4; mI++) {
        int r0 = m0 + wm + mI * 16 + g;
        int bi0 = r0 >> 11, t0 = r0 & (TT - 1);
        #pragma unroll
        for (int n = 0; n < 4; n++) {
            int e = n0 + wn + n * 8 + 2 * t;
            float bb0 = bias[e], bb1 = bias[e + 1];
            float v00 = acc[mI][n][0] + bb0, v01 = acc[mI][n][1] + bb1;
            float v10 = acc[mI][n][2] + bb0, v11 = acc[mI][n][3] + bb1;
            int h = e >> 6, dk = e & 63;
            int cl = dk & 15;
            int pos = (((cl >> 1) & 3) << 2) + (((cl >> 3) & 1) << 1);
            int dkp = (dk & ~15) + pos;
            size_t base0 = (((size_t)(bi0 * HH + h) * TT + t0) << 6);
            size_t base1 = base0 + (8 << 6);
            *(__nv_bfloat162*)&C[base0 + dkp] = __floats2bfloat162_rn(v00, v01);
            *(__nv_bfloat162*)&C[base1 + dkp] = __floats2bfloat162_rn(v10, v11);
        }
    }
}

// ---------------- fp16 GEMM for V (mode 2) and O (mode 3): 3-stage ---------
__global__ __launch_bounds__(256) void gemm_vo_kernel(
    const float* __restrict__ bias, int mode, float* __restrict__ dout) {
    extern __shared__ __half fsm[];
    const __half* W = g_wcf + (size_t)(mode == 3 ? 1 : 0) * DD * DD;
    const __half* Aptr = (mode == 2) ? g_xnf : g_aoh;

    int tid  = threadIdx.x;
    int wid  = tid >> 5;
    int lane = tid & 31;
    int g = lane >> 2, t = lane & 3;
    int wm = (wid >> 2) * 64;
    int wn = (wid & 3) * 32;
    int m0 = blockIdx.y * 128;
    int n0 = blockIdx.x * 128;
    uint32_t sbase = smem_u32(fsm);

    float acc[4][4][4];
    #pragma unroll
    for (int i = 0; i < 4; i++)
        #pragma unroll
        for (int j = 0; j < 4; j++)
            #pragma unroll
            for (int e = 0; e < 4; e++) acc[i][j][e] = 0.f;

    auto load_stage = [&](int k0, int st) {
        #pragma unroll
        for (int p = 0; p < 2; p++) {
            int slot = tid + p * 256;
            int row  = slot >> 2;
            int col8 = (slot & 3) * 8;
            cp_async16(sbase + (uint32_t)((st * HTILE + row * HSTR + col8) * 2),
                       &Aptr[(size_t)(m0 + row) * DD + k0 + col8]);
            cp_async16(sbase + (uint32_t)(((3 + st) * HTILE + row * HSTR + col8) * 2),
                       &W[(size_t)(n0 + row) * DD + k0 + col8]);
        }
        cp_commit();
    };

    load_stage(0, 0);
    load_stage(32, 1);
    for (int it = 0; it < NIT; it++) {
        int cur = it % 3;
        if (it + 1 < NIT) cp_wait1(); else cp_wait0();
        __syncthreads();
        if (it + 2 < NIT) load_stage((it + 2) * 32, (it + 2) % 3);
        const __half* As = fsm + cur * HTILE;
        const __half* Bs = fsm + (3 + cur) * HTILE;
        #pragma unroll
        for (int ks = 0; ks < 2; ks++) {
            int kc = ks * 16 + 4 * t;
            unsigned bf[4][2];
            #pragma unroll
            for (int n = 0; n < 4; n++) {
                uint2 bb = *(const uint2*)&Bs[(wn + n * 8 + g) * HSTR + kc];
                bf[n][0] = bb.x; bf[n][1] = bb.y;
            }
            #pragma unroll
            for (int mI = 0; mI < 4; mI++) {
                int rb = wm + mI * 16;
                uint2 aA = *(const uint2*)&As[(rb + g) * HSTR + kc];
                uint2 aB = *(const uint2*)&As[(rb + g + 8) * HSTR + kc];
                unsigned af[4] = {aA.x, aB.x, aA.y, aB.y};
                #pragma unroll
                for (int n = 0; n < 4; n++)
                    mma_f16(acc[mI][n], af, bf[n], acc[mI][n]);
            }
        }
    }

    #pragma unroll
    for (int mI = 0; mI < 4; mI++) {
        int r0 = m0 + wm + mI * 16 + g;
        int bi0 = r0 >> 11, t0 = r0 & (TT - 1);
        #pragma unroll
        for (int n = 0; n < 4; n++) {
            int e = n0 + wn + n * 8 + 2 * t;
            float bb0 = bias[e], bb1 = bias[e + 1];
            float v00 = acc[mI][n][0] + bb0, v01 = acc[mI][n][1] + bb1;
            float v10 = acc[mI][n][2] + bb0, v11 = acc[mI][n][3] + bb1;
            if (mode == 3) {
                *(float2*)&dout[(size_t)r0 * DD + e] =
                    make_float2(v00 * 0.5f, v01 * 0.5f);
                *(float2*)&dout[(size_t)(r0 + 8) * DD + e] =
                    make_float2(v10 * 0.5f, v11 * 0.5f);
            } else {
                int h = e >> 6, dk = e & 63;
                int kt0 = t0 >> 6, ik = t0 & 63;
                int pk = (ik & ~15) | perm16(ik & 15);
                __half* vb = g_vh +
                    ((((size_t)(bi0 * HH + h) * (TT / 64) + kt0) * DKK + dk) << 6);
                vb[pk]          = __float2half_rn(v00);
                vb[64 + pk]     = __float2half_rn(v01);
                vb[pk + 2]      = __float2half_rn(v10);
                vb[64 + pk + 2] = __float2half_rn(v11);
            }
        }
    }
}

// ---------------- L2 normalize Q,K (bf16, order-invariant) ----------------
__global__ __launch_bounds__(256) void l2norm_kernel() {
    int warp = (blockIdx.x * blockDim.x + threadIdx.x) >> 5;
    int lane = threadIdx.x & 31;
    __nv_bfloat162* base =
        (__nv_bfloat162*)((blockIdx.y == 0) ? g_qh : g_kh);
    __nv_bfloat162* p = base + (size_t)warp * 32 + lane;
    float2 v = __bfloat1622float2(*p);
    float ss = v.x * v.x + v.y * v.y;
    #pragma unroll
    for (int o = 16; o > 0; o >>= 1) ss += __shfl_xor_sync(~0u, ss, o);
    float n = sqrtf(ss);
    float inv = 1.0f / fmaxf(n, EPS_NORM_);
    *p = __floats2bfloat162_rn(v.x * inv, v.y * inv);
}

// ---------------- Flash attention: bf16 S, fp16 PV ----------------
#define KH_STR 80
#define KH_TILE_B (64 * KH_STR * 2)
#define VH_STR 80
#define VH_TILE_B (64 * VH_STR * 2)
#define VT_OFF_B (2 * KH_TILE_B)
#define P_OFF_B (VT_OFF_B + 2 * VH_TILE_B)
#define MSK_OFF_B (P_OFF_B + VH_TILE_B)
#define ASMEM (MSK_OFF_B + TT)
__global__ __launch_bounds__(128) void attn_tc_kernel() {
    extern __shared__ char asmb[];
    unsigned char* Msk = (unsigned char*)(asmb + MSK_OFF_B);
    __half* Ps = (__half*)(asmb + P_OFF_B);

    int bh = blockIdx.y;
    int bi = bh >> 4;
    int h  = bh & 15;
    int qt = blockIdx.x;
    int tid = threadIdx.x;
    int wid = tid >> 5;
    int lane = tid & 31;
    int g = lane >> 2, t = lane & 3;
    int wg = wid * 16;
    uint32_t sbase = smem_u32(asmb);

    ((uint4*)Msk)[tid] = ((const uint4*)(g_cmask + bi * TT))[tid];

    unsigned qa[4][4];
    {
        const __nv_bfloat16* qp0 =
            g_qh + (((size_t)(bh * TT + qt * 64 + wg + g)) << 6);
        const __nv_bfloat16* qp1 = qp0 + (8 << 6);
        #pragma unroll
        for (int ks = 0; ks < 4; ks++) {
            uint2 xA = *(const uint2*)&qp0[ks * 16 + 4 * t];
            uint2 xB = *(const uint2*)&qp1[ks * 16 + 4 * t];
            qa[ks][0] = xA.x; qa[ks][1] = xB.x;
            qa[ks][2] = xA.y; qa[ks][3] = xB.y;
        }
    }

    float o_acc[8][4];
    #pragma unroll
    for (int n = 0; n < 8; n++)
        #pragma unroll
        for (int e = 0; e < 4; e++) o_acc[n][e] = 0.f;
    float psum0 = 0.f, psum1 = 0.f;

    const __nv_bfloat16* kbase = g_kh + (((size_t)bh * TT) << 6);
    const __half* vbase = g_vh + (((size_t)bh * TT) << 6);

    auto load_kv = [&](int kt, int st) {
        const __nv_bfloat16* kb = kbase + ((size_t)(kt * 64) << 6);
        const __half* vb = vbase + ((size_t)kt << 12);
        #pragma unroll
        for (int p = 0; p < 4; p++) {
            int slot = tid + p * 128;
            int row  = slot >> 3;
            int col8 = (slot & 7) * 8;
            cp_async16(sbase + (uint32_t)(st * KH_TILE_B + (row * KH_STR + col8) * 2),
                       &kb[(row << 6) + col8]);
        }
        #pragma unroll
        for (int p = 0; p < 4; p++) {
            int slot = tid + p * 128;
            int row  = slot >> 3;
            int col8 = (slot & 7) * 8;
            cp_async16(sbase + (uint32_t)(VT_OFF_B + st * VH_TILE_B +
                                          (row * VH_STR + col8) * 2),
                       &vb[(row << 6) + col8]);
        }
        cp_commit();
    };

    load_kv(0, 0);
    for (int kt = 0; kt < TT / 64; kt++) {
        int cur = kt & 1;
        cp_wait0();
        __syncthreads();
        if (kt < TT / 64 - 1) load_kv(kt + 1, cur ^ 1);

        const __nv_bfloat16* Ks = (const __nv_bfloat16*)(asmb + cur * KH_TILE_B);
        const __half* Vs = (const __half*)(asmb + VT_OFF_B + cur * VH_TILE_B);

        // S = Q.K^T (bf16)
        float sc[8][4];
        #pragma unroll
        for (int n = 0; n < 8; n++)
            #pragma unroll
            for (int e = 0; e < 4; e++) sc[n][e] = 0.f;
        #pragma unroll
        for (int ks = 0; ks < 4; ks++) {
            int kc = ks * 16 + 4 * t;
            #pragma unroll
            for (int n = 0; n < 8; n++) {
                uint2 kb2 = *(const uint2*)&Ks[(n * 8 + g) * KH_STR + kc];
                unsigned bf[2] = {kb2.x, kb2.y};
                mma_bf16(sc[n], qa[ks], bf, sc[n]);
            }
        }

        // static softmax via ex2 (SCALE folded); masked -> 0
        const unsigned char* mrow = Msk + kt * 64;
        #pragma unroll
        for (int n = 0; n < 8; n++) {
            bool mk0 = mrow[n * 8 + 2 * t] != 0;
            bool mk1 = mrow[n * 8 + 2 * t + 1] != 0;
            sc[n][0] = mk0 ? 0.f : fexp2(sc[n][0] * SC2_);
            sc[n][1] = mk1 ? 0.f : fexp2(sc[n][1] * SC2_);
            sc[n][2] = mk0 ? 0.f : fexp2(sc[n][2] * SC2_);
            sc[n][3] = mk1 ? 0.f : fexp2(sc[n][3] * SC2_);
            psum0 += sc[n][0] + sc[n][1];
            psum1 += sc[n][2] + sc[n][3];
        }

        // P fp16 -> warp-private rows, key-perm16 columns
        #pragma unroll
        for (int n = 0; n < 8; n++) {
            int pc = (n >> 1) * 16 + 4 * t + 2 * (n & 1);
            *(__half2*)&Ps[(wg + g) * VH_STR + pc] =
                __floats2half2_rn(sc[n][0], sc[n][1]);
            *(__half2*)&Ps[(wg + g + 8) * VH_STR + pc] =
                __floats2half2_rn(sc[n][2], sc[n][3]);
        }
        __syncwarp();

        // O += P.V (fp16 m16n8k16)
        #pragma unroll
        for (int ks = 0; ks < 4; ks++) {
            int kc = ks * 16 + 4 * t;
            uint2 pA = *(const uint2*)&Ps[(wg + g) * VH_STR + kc];
            uint2 pB = *(const uint2*)&Ps[(wg + g + 8) * VH_STR + kc];
            unsigned pa[4] = {pA.x, pB.x, pA.y, pB.y};
            #pragma unroll
            for (int n = 0; n < 8; n++) {
                uint2 vb2 = *(const uint2*)&Vs[(n * 8 + g) * VH_STR + kc];
                unsigned bf[2] = {vb2.x, vb2.y};
                mma_f16(o_acc[n], pa, bf, o_acc[n]);
            }
        }
        __syncwarp();
    }

    psum0 += __shfl_xor_sync(~0u, psum0, 1);
    psum0 += __shfl_xor_sync(~0u, psum0, 2);
    psum1 += __shfl_xor_sync(~0u, psum1, 1);
    psum1 += __shfl_xor_sync(~0u, psum1, 2);
    float inv0 = 1.0f / psum0;
    float inv1 = 1.0f / psum1;
    int tq0 = qt * 64 + wg + g;
    __half* ob0 = g_aoh + ((size_t)bi * TT + tq0) * DD + h * 64;
    __half* ob1 = ob0 + 8 * DD;
    #pragma unroll
    for (int n = 0; n < 8; n++) {
        int pc = (n >> 1) * 16 + 4 * t + 2 * (n & 1);
        *(__half2*)&ob0[pc] =
            __floats2half2_rn(o_acc[n][0] * inv0, o_acc[n][1] * inv0);
        *(__half2*)&ob1[pc] =
            __floats2half2_rn(o_acc[n][2] * inv1, o_acc[n][3] * inv1);
    }
}

// ---------------- launch ----------------
extern "C" void kernel_launch(void* const* d_in, const int* in_sizes, int n_in,
                              void* d_out, int out_size) {
    const float* x    = (const float*)d_in[0];
    const void*  mask = d_in[1];
    const float* wq = (const float*)d_in[2];
    const float* bq = (const float*)d_in[3];
    const float* wk = (const float*)d_in[4];
    const float* bk = (const float*)d_in[5];
    const float* wv = (const float*)d_in[6];
    const float* bv = (const float*)d_in[7];
    const float* wo = (const float*)d_in[8];
    const float* bo = (const float*)d_in[9];
    const float* ln_g = (const float*)d_in[10];
    const float* ln_b = (const float*)d_in[11];
    float* out = (float*)d_out;

    const int h_smem    = 6 * HTILE * 2;             // 73728 B (3-stage)
    const int attn_smem = ASMEM;                     // 53248 B
    cudaFuncSetAttribute(gemm_qk_kernel,
        cudaFuncAttributeMaxDynamicSharedMemorySize, h_smem);
    cudaFuncSetAttribute(gemm_vo_kernel,
        cudaFuncAttributeMaxDynamicSharedMemorySize, h_smem);
    cudaFuncSetAttribute(attn_tc_kernel,
        cudaFuncAttributeMaxDynamicSharedMemorySize, attn_smem);

    detect_mask_kernel<<<1, 256>>>((const unsigned char*)mask);
    convert_mask_kernel<<<(BB * TT + 255) / 256, 256>>>(mask);
    wconv_kernel<<<dim3(DD * DD / 1024, 4), 256>>>(wq, wk, wv, wo);
    ln_kernel<<<BB * TT, 256>>>(x, ln_g, ln_b);

    dim3 qk_grid(DD / 128, (BB * TT) / 128, 2);
    gemm_qk_kernel<<<qk_grid, 256, h_smem>>>(bq, bk);

    dim3 vgrid(DD / 128, (BB * TT) / 128);
    gemm_vo_kernel<<<vgrid, 256, h_smem>>>(bv, 2, nullptr);

    dim3 l2grid((BB * HH * TT) / 8, 2);
    l2norm_kernel<<<l2grid, 256>>>();

    dim3 agrid(TT / 64, BB * HH);
    attn_tc_kernel<<<agrid, 128, attn_smem>>>();

    gemm_vo_kernel<<<vgrid, 256, h_smem>>>(bo, 3, out);
}